// round 12
// baseline (speedup 1.0000x reference)
#include <cuda_runtime.h>
#include <cuda_fp16.h>
#include <cstdint>

// ============================================================================
// BiBoSparseMoeBlock: top-2-of-8 MoE SwiGLU, fp32 in/out.
// Round 12: R10 champion shape (warp 32x32, CTA 128x64, 256 thr, 2 CTA/SM,
// 3-stage wait_group(1)) with BK=64 stages (half the syncs) and one fewer
// launch (counting offsets kernel).
// ============================================================================

#define HID   2048
#define INTER 1024
#define NEXP  8
#define MAXT  4096
#define MAXSLOTS (2 * MAXT)

typedef unsigned int u32;

// ---- device scratch ---------------------------------------------------------
__device__ int   g_cnt[NEXP];
__device__ int   g_off[NEXP];
__device__ int   g_fill[NEXP];
__device__ int   g_perm[MAXSLOTS];
__device__ float g_w[MAXSLOTS];
__device__ int   g_tidx[MAXT * 2];
__device__ float g_tw[MAXT * 2];
__device__ int   g_slot_of[MAXT * 2];

__device__ __half g_X16[(size_t)MAXT * HID];
__device__ __half g_Wg16[(size_t)NEXP * INTER * HID];
__device__ __half g_Wu16[(size_t)NEXP * INTER * HID];
__device__ __half g_Wd16[(size_t)NEXP * HID * INTER];
__device__ __half g_H16[(size_t)MAXSLOTS * INTER];
__device__ float  g_y[(size_t)MAXSLOTS * HID];

// ---- PTX helpers (baseline sm_80-era only) -------------------------------------
__device__ __forceinline__ u32 smem_u32(const void* p) {
    u32 a;
    asm("{ .reg .u64 t; cvta.to.shared.u64 t, %1; cvt.u32.u64 %0, t; }" : "=r"(a) : "l"(p));
    return a;
}
__device__ __forceinline__ void cpa16(u32 dst, const void* src) {
    asm volatile("cp.async.cg.shared.global [%0], [%1], 16;" :: "r"(dst), "l"(src));
}
#define CPA_COMMIT() asm volatile("cp.async.commit_group;" ::: "memory")
#define CPA_WAIT1()  asm volatile("cp.async.wait_group 1;" ::: "memory")
#define CPA_WAIT0()  asm volatile("cp.async.wait_group 0;" ::: "memory")

__device__ __forceinline__ void ldsm4(u32* r, u32 addr) {
    asm volatile("ldmatrix.sync.aligned.m8n8.x4.shared.b16 {%0,%1,%2,%3}, [%4];"
                 : "=r"(r[0]), "=r"(r[1]), "=r"(r[2]), "=r"(r[3]) : "r"(addr));
}
__device__ __forceinline__ void mma16816(float* c, const u32* a, u32 b0, u32 b1) {
    asm volatile(
        "mma.sync.aligned.m16n8k16.row.col.f32.f16.f16.f32 "
        "{%0,%1,%2,%3}, {%4,%5,%6,%7}, {%8,%9}, {%0,%1,%2,%3};"
        : "+f"(c[0]), "+f"(c[1]), "+f"(c[2]), "+f"(c[3])
        : "r"(a[0]), "r"(a[1]), "r"(a[2]), "r"(a[3]), "r"(b0), "r"(b1));
}

// ---- smem geometry: BK=64 fp16 rows (128B data), pitch 144B --------------------
// bank-group(r,c16) = (9r + c) mod 8 = (r + c) mod 8: permutation in r ->
// conflict-free for ldmatrix 8-row reads and balanced for cp.async.
#define PITCH 144
#define OFF_A  0                 // A: 128 rows * 144 = 18432
#define OFF_B  18432             // B: 64 rows * 144 = 9216
#define STAGE_BYTES 27648
#define NSTAGE 3
#define SMEM_DYN (NSTAGE * STAGE_BYTES)   // 82944 -> 2 CTAs/SM

// ---- small kernels --------------------------------------------------------------
__global__ void router_kernel(const float* __restrict__ x,
                              const float* __restrict__ Wr,
                              float* __restrict__ logits_out, int write_logits) {
    const int t = blockIdx.x;
    const int warp = threadIdx.x >> 5;
    const int lane = threadIdx.x & 31;
    __shared__ float slog[NEXP];
    const float* xr = x + (size_t)t * HID;
    const float* wr = Wr + (size_t)warp * HID;
    float s = 0.0f;
    #pragma unroll 4
    for (int i = lane; i < HID; i += 32) s += xr[i] * wr[i];
    #pragma unroll
    for (int o = 16; o > 0; o >>= 1) s += __shfl_xor_sync(0xffffffffu, s, o);
    if (lane == 0) slog[warp] = s;
    __syncthreads();
    if (write_logits && threadIdx.x < NEXP)
        logits_out[t * NEXP + threadIdx.x] = slog[threadIdx.x];
    if (threadIdx.x == 0) {
        float v0 = -1e30f; int i0 = 0;
        #pragma unroll
        for (int i = 0; i < NEXP; i++) if (slog[i] > v0) { v0 = slog[i]; i0 = i; }
        float v1 = -1e30f; int i1 = 0;
        #pragma unroll
        for (int i = 0; i < NEXP; i++)
            if (i != i0 && slog[i] > v1) { v1 = slog[i]; i1 = i; }
        float ex = expf(v1 - v0);
        float inv = 1.0f / (1.0f + ex);
        g_tidx[2 * t] = i0; g_tidx[2 * t + 1] = i1;
        g_tw[2 * t] = inv;  g_tw[2 * t + 1] = ex * inv;
    }
}

// counting offsets: histogram g_tidx in one block (no pre-zero kernel needed)
__global__ void offsets_kernel(int T) {
    __shared__ int hist[NEXP];
    if (threadIdx.x < NEXP) hist[threadIdx.x] = 0;
    __syncthreads();
    for (int i = threadIdx.x; i < 2 * T; i += blockDim.x)
        atomicAdd(&hist[g_tidx[i]], 1);
    __syncthreads();
    if (threadIdx.x == 0) {
        int o = 0;
        #pragma unroll
        for (int e = 0; e < NEXP; e++) {
            g_cnt[e] = hist[e];
            g_off[e] = o;
            g_fill[e] = 0;
            o += hist[e];
        }
    }
}

__global__ void scatter_kernel(int T) {
    int t = blockIdx.x * blockDim.x + threadIdx.x;
    if (t >= T) return;
    #pragma unroll
    for (int j = 0; j < 2; j++) {
        int e = g_tidx[2 * t + j];
        int p = atomicAdd(&g_fill[e], 1);
        int slot = g_off[e] + p;
        g_perm[slot] = t;
        g_w[slot] = g_tw[2 * t + j];
        g_slot_of[2 * t + j] = slot;
    }
}

// ---- conversion pre-pass: fp32 -> fp16 ------------------------------------------
__device__ __forceinline__ uint2 f4_to_h4(const float4 v) {
    __half2 a = __floats2half2_rn(v.x, v.y);
    __half2 b = __floats2half2_rn(v.z, v.w);
    return make_uint2(*(u32*)&a, *(u32*)&b);
}

__global__ void split_all_kernel(const float* __restrict__ x,
                                 const float* __restrict__ Wg,
                                 const float* __restrict__ Wu,
                                 const float* __restrict__ Wd, int nx, int nw) {
    int i = blockIdx.x * blockDim.x + threadIdx.x;
    if (i < nx) {
        ((uint2*)g_X16)[i] = f4_to_h4(((const float4*)x)[i]);
    } else if (i < nx + nw) {
        int j = i - nx;
        ((uint2*)g_Wg16)[j] = f4_to_h4(((const float4*)Wg)[j]);
    } else if (i < nx + 2 * nw) {
        int j = i - nx - nw;
        ((uint2*)g_Wu16)[j] = f4_to_h4(((const float4*)Wu)[j]);
    } else if (i < nx + 3 * nw) {
        int j = i - nx - 2 * nw;
        ((uint2*)g_Wd16)[j] = f4_to_h4(((const float4*)Wd)[j]);
    }
}

// ---- GEMM 1: gate+up. CTA: 128 slots x (32 gate + 32 up), warp 32x32, BK=64 -----
__global__ __launch_bounds__(256, 2) void gateup_mma_kernel() {
    const int e   = blockIdx.z;
    const int cnt = g_cnt[e];
    const int m0  = blockIdx.y * 128;
    if (m0 >= cnt) return;
    const int rows = min(cnt - m0, 128);
    const int base = g_off[e] + m0;
    const int n0   = blockIdx.x * 32;

    extern __shared__ char dsm[];
    const u32 sm0 = smem_u32(dsm);

    const int tid  = threadIdx.x;
    const int lane = tid & 31;
    const int wid  = tid >> 5;
    const int wm   = wid >> 1;          // 0..3 -> 32-row band
    const int wn   = wid & 1;           // 0 = gate cols, 1 = up cols

    // ---- loader: stage = A 128x128B + B 64x128B = 1536 16B-chunks, 6/thread ----
    // A: thread q=tid>>1 handles row q (c2=tid&1 -> 2 chunks of 4), rows 0..127
    const int qa = tid >> 1;            // 0..127: A row
    const int ca = (tid & 1) * 64;      // byte offset half (two 16B per half... )
    // Each thread does 4 cp.async for A (its half-row: 64B) and 2 for B.
    const int ra = min(qa, rows - 1);
    const size_t xoff = (size_t)g_perm[base + ra] * HID + (ca / 2);  // fp16 elems
    const u32 dA = (u32)(OFF_A + qa * PITCH + ca);
    // B: thread (tid & 127) >> 1 ... B has 64 rows x 128B = 512 chunks; use
    // threads 0..255: q_b = tid >> 2 (0..63), cb = (tid & 3) * 32 bytes
    const int qb = tid >> 2;            // 0..63
    const int cb = (tid & 3) * 32;      // 32B per thread => 2 cp.async
    const __half* pbase;
    if (qb < 32) pbase = g_Wg16 + ((size_t)e * INTER + n0 + qb) * HID + cb / 2;
    else         pbase = g_Wu16 + ((size_t)e * INTER + n0 + (qb - 32)) * HID + cb / 2;
    const u32 dB = (u32)(OFF_B + qb * PITCH + cb);

    // ---- ldmatrix bases (pitch 144) ----
    const u32 a_off = (u32)((wm * 32 + (lane & 7) + ((lane >> 3) & 1) * 8) * PITCH
                    + (lane >> 4) * 16);
    const u32 b_off0 = (u32)((wn * 32 + (lane & 7) + (lane >> 4) * 8) * PITCH
                    + ((lane >> 3) & 1) * 16);
    const u32 b_off1 = b_off0 + 16 * PITCH;

    float acc[2][4][4];
    #pragma unroll
    for (int i = 0; i < 2; i++)
        #pragma unroll
        for (int j = 0; j < 4; j++)
            #pragma unroll
            for (int k = 0; k < 4; k++) acc[i][j][k] = 0.0f;

    const int KT = HID / 64;            // 32 stages

    #pragma unroll
    for (int p = 0; p < NSTAGE - 1; p++) {
        const u32 sb = sm0 + (u32)p * STAGE_BYTES;
        const size_t ko = (size_t)p * 64;
        #pragma unroll
        for (int c = 0; c < 4; c++) cpa16(sb + dA + c * 16, g_X16 + xoff + ko + c * 8);
        #pragma unroll
        for (int c = 0; c < 2; c++) cpa16(sb + dB + c * 16, pbase + ko + c * 8);
        CPA_COMMIT();
    }

    #pragma unroll 1
    for (int kt = 0; kt < KT; kt++) {
        if (kt == KT - 1) CPA_WAIT0(); else CPA_WAIT1();
        __syncthreads();
        if (kt + NSTAGE - 1 < KT) {
            const u32 sb = sm0 + (u32)((kt + NSTAGE - 1) % NSTAGE) * STAGE_BYTES;
            const size_t ko = (size_t)(kt + NSTAGE - 1) * 64;
            #pragma unroll
            for (int c = 0; c < 4; c++) cpa16(sb + dA + c * 16, g_X16 + xoff + ko + c * 8);
            #pragma unroll
            for (int c = 0; c < 2; c++) cpa16(sb + dB + c * 16, pbase + ko + c * 8);
            CPA_COMMIT();
        }
        const u32 sb = sm0 + (u32)(kt % NSTAGE) * STAGE_BYTES;
        #pragma unroll
        for (int ks = 0; ks < 4; ks++) {
            u32 ah[2][4], bh[2][4];
            #pragma unroll
            for (int mi = 0; mi < 2; mi++)
                ldsm4(ah[mi], sb + OFF_A + a_off + (u32)(mi * 16 * PITCH) + (u32)(ks * 32));
            ldsm4(bh[0], sb + OFF_B + b_off0 + (u32)(ks * 32));
            ldsm4(bh[1], sb + OFF_B + b_off1 + (u32)(ks * 32));
            #pragma unroll
            for (int mi = 0; mi < 2; mi++) {
                #pragma unroll
                for (int ni = 0; ni < 4; ni++) {
                    const int g = ni >> 1, s = (ni & 1) * 2;
                    mma16816(acc[mi][ni], ah[mi], bh[g][s], bh[g][s + 1]);
                }
            }
        }
    }
    __syncthreads();

    // ---- epilogue: exchange via smem (128 x 72 f32), silu(g)*u, store fp16 ----
    float* S = (float*)dsm;
    #pragma unroll
    for (int mi = 0; mi < 2; mi++) {
        const int rr = wm * 32 + mi * 16 + (lane >> 2);
        #pragma unroll
        for (int ni = 0; ni < 4; ni++) {
            const int cc = wn * 32 + ni * 8 + 2 * (lane & 3);
            *(float2*)(S + (size_t)rr * 72 + cc)       = make_float2(acc[mi][ni][0], acc[mi][ni][1]);
            *(float2*)(S + (size_t)(rr + 8) * 72 + cc) = make_float2(acc[mi][ni][2], acc[mi][ni][3]);
        }
    }
    __syncthreads();
    {
        const int row  = tid >> 1;
        const int half = (tid & 1) * 16;
        if (row < rows) {
            u32 ph[8];
            #pragma unroll
            for (int p = 0; p < 8; p++) {
                float g0 = S[(size_t)row * 72 + half + 2 * p];
                float g1 = S[(size_t)row * 72 + half + 2 * p + 1];
                float u0 = S[(size_t)row * 72 + 32 + half + 2 * p];
                float u1 = S[(size_t)row * 72 + 32 + half + 2 * p + 1];
                float h0 = (g0 / (1.0f + expf(-g0))) * u0;
                float h1 = (g1 / (1.0f + expf(-g1))) * u1;
                __half2 A = __floats2half2_rn(h0, h1);
                ph[p] = *(u32*)&A;
            }
            u32* dh = (u32*)(g_H16 + (size_t)(base + row) * INTER + n0 + half);
            ((uint4*)dh)[0] = make_uint4(ph[0], ph[1], ph[2], ph[3]);
            ((uint4*)dh)[1] = make_uint4(ph[4], ph[5], ph[6], ph[7]);
        }
    }
}

// ---- GEMM 2: down. CTA: 128 slots x 64 hid, warp 32x32, BK=64, K=1024 ------------
__global__ __launch_bounds__(256, 2) void down_mma_kernel() {
    const int e   = blockIdx.z;
    const int cnt = g_cnt[e];
    const int m0  = blockIdx.y * 128;
    if (m0 >= cnt) return;
    const int rows = min(cnt - m0, 128);
    const int base = g_off[e] + m0;
    const int n0   = blockIdx.x * 64;

    extern __shared__ char dsm[];
    const u32 sm0 = smem_u32(dsm);

    const int tid  = threadIdx.x;
    const int lane = tid & 31;
    const int wid  = tid >> 5;
    const int wm   = wid >> 1;
    const int wn   = wid & 1;

    const int qa = tid >> 1;
    const int ca = (tid & 1) * 64;
    const int ra = min(qa, rows - 1);
    const size_t hoff = (size_t)(base + ra) * INTER + (ca / 2);
    const u32 dA = (u32)(OFF_A + qa * PITCH + ca);
    const int qb = tid >> 2;
    const int cb = (tid & 3) * 32;
    const __half* pbase = g_Wd16 + ((size_t)e * HID + n0 + qb) * INTER + cb / 2;
    const u32 dB = (u32)(OFF_B + qb * PITCH + cb);

    const u32 a_off = (u32)((wm * 32 + (lane & 7) + ((lane >> 3) & 1) * 8) * PITCH
                    + (lane >> 4) * 16);
    const u32 b_off0 = (u32)((wn * 32 + (lane & 7) + (lane >> 4) * 8) * PITCH
                    + ((lane >> 3) & 1) * 16);
    const u32 b_off1 = b_off0 + 16 * PITCH;

    float acc[2][4][4];
    #pragma unroll
    for (int i = 0; i < 2; i++)
        #pragma unroll
        for (int j = 0; j < 4; j++)
            #pragma unroll
            for (int k = 0; k < 4; k++) acc[i][j][k] = 0.0f;

    const int KT = INTER / 64;          // 16 stages

    #pragma unroll
    for (int p = 0; p < NSTAGE - 1; p++) {
        const u32 sb = sm0 + (u32)p * STAGE_BYTES;
        const size_t ko = (size_t)p * 64;
        #pragma unroll
        for (int c = 0; c < 4; c++) cpa16(sb + dA + c * 16, g_H16 + hoff + ko + c * 8);
        #pragma unroll
        for (int c = 0; c < 2; c++) cpa16(sb + dB + c * 16, pbase + ko + c * 8);
        CPA_COMMIT();
    }

    #pragma unroll 1
    for (int kt = 0; kt < KT; kt++) {
        if (kt == KT - 1) CPA_WAIT0(); else CPA_WAIT1();
        __syncthreads();
        if (kt + NSTAGE - 1 < KT) {
            const u32 sb = sm0 + (u32)((kt + NSTAGE - 1) % NSTAGE) * STAGE_BYTES;
            const size_t ko = (size_t)(kt + NSTAGE - 1) * 64;
            #pragma unroll
            for (int c = 0; c < 4; c++) cpa16(sb + dA + c * 16, g_H16 + hoff + ko + c * 8);
            #pragma unroll
            for (int c = 0; c < 2; c++) cpa16(sb + dB + c * 16, pbase + ko + c * 8);
            CPA_COMMIT();
        }
        const u32 sb = sm0 + (u32)(kt % NSTAGE) * STAGE_BYTES;
        #pragma unroll
        for (int ks = 0; ks < 4; ks++) {
            u32 ah[2][4], bh[2][4];
            #pragma unroll
            for (int mi = 0; mi < 2; mi++)
                ldsm4(ah[mi], sb + OFF_A + a_off + (u32)(mi * 16 * PITCH) + (u32)(ks * 32));
            ldsm4(bh[0], sb + OFF_B + b_off0 + (u32)(ks * 32));
            ldsm4(bh[1], sb + OFF_B + b_off1 + (u32)(ks * 32));
            #pragma unroll
            for (int mi = 0; mi < 2; mi++) {
                #pragma unroll
                for (int ni = 0; ni < 4; ni++) {
                    const int g = ni >> 1, s = (ni & 1) * 2;
                    mma16816(acc[mi][ni], ah[mi], bh[g][s], bh[g][s + 1]);
                }
            }
        }
    }

    // ---- epilogue: scale by routing weight, store f32 ----
    #pragma unroll
    for (int mi = 0; mi < 2; mi++) {
        const int r0o = wm * 32 + mi * 16 + (lane >> 2);
        const int r1o = r0o + 8;
        const float w0 = (r0o < rows) ? g_w[base + r0o] : 0.0f;
        const float w1 = (r1o < rows) ? g_w[base + r1o] : 0.0f;
        #pragma unroll
        for (int ni = 0; ni < 4; ni++) {
            const int cc = n0 + wn * 32 + ni * 8 + 2 * (lane & 3);
            if (r0o < rows)
                *(float2*)(g_y + (size_t)(base + r0o) * HID + cc) =
                    make_float2(w0 * acc[mi][ni][0], w0 * acc[mi][ni][1]);
            if (r1o < rows)
                *(float2*)(g_y + (size_t)(base + r1o) * HID + cc) =
                    make_float2(w1 * acc[mi][ni][2], w1 * acc[mi][ni][3]);
        }
    }
}

// ---- combine: out[t] = y[slot0] + y[slot1] ----------------------------------------
__global__ void combine_kernel(float* __restrict__ out, int T) {
    const int gid = blockIdx.x * blockDim.x + threadIdx.x;
    const int per_tok = HID / 4;
    if (gid >= T * per_tok) return;
    const int t = gid / per_tok;
    const int c = gid - t * per_tok;
    const int s0 = g_slot_of[2 * t];
    const int s1 = g_slot_of[2 * t + 1];
    float4 a = ((const float4*)(g_y + (size_t)s0 * HID))[c];
    float4 b = ((const float4*)(g_y + (size_t)s1 * HID))[c];
    ((float4*)(out + (size_t)t * HID))[c] =
        make_float4(a.x + b.x, a.y + b.y, a.z + b.z, a.w + b.w);
}

// ---- launch -------------------------------------------------------------------------
extern "C" void kernel_launch(void* const* d_in, const int* in_sizes, int n_in,
                              void* d_out, int out_size) {
    if (n_in < 5) return;
    const float* x  = (const float*)d_in[0];
    const float* Wr = (const float*)d_in[1];
    const float* Wg = (const float*)d_in[2];
    const float* Wu = (const float*)d_in[3];
    const float* Wd = (const float*)d_in[4];
    float* out = (float*)d_out;

    int T = in_sizes[0] / HID;
    if (T > MAXT) T = MAXT;

    cudaFuncSetAttribute(gateup_mma_kernel, cudaFuncAttributeMaxDynamicSharedMemorySize, SMEM_DYN);
    cudaFuncSetAttribute(down_mma_kernel,   cudaFuncAttributeMaxDynamicSharedMemorySize, SMEM_DYN);

    const int write_logits = (out_size >= T * HID + T * NEXP);
    float* logits = out + (size_t)T * HID;

    router_kernel<<<T, 256>>>(x, Wr, logits, write_logits);
    offsets_kernel<<<1, 256>>>(T);
    scatter_kernel<<<(T + 255) / 256, 256>>>(T);

    const int nx = T * HID / 4;
    const int nw = NEXP * INTER * HID / 4;
    split_all_kernel<<<(nx + 3 * nw + 255) / 256, 256>>>(x, Wg, Wu, Wd, nx, nw);

    gateup_mma_kernel<<<dim3(INTER / 32, MAXSLOTS / 128, NEXP), 256, SMEM_DYN>>>();
    down_mma_kernel<<<dim3(HID / 64, MAXSLOTS / 128, NEXP), 256, SMEM_DYN>>>();

    combine_kernel<<<(T * (HID / 4) + 255) / 256, 256>>>(out, T);
}

// round 13
// speedup vs baseline: 1.2694x; 1.2694x over previous
#include <cuda_runtime.h>
#include <cuda_fp16.h>
#include <cstdint>

// ============================================================================
// BiBoSparseMoeBlock: top-2-of-8 MoE SwiGLU, fp32 in/out.
// Round 13: exact R10 champion GEMMs (warp 32x32, CTA 128x64, BK=32, 256 thr,
// 2 CTA/SM, 3-stage wait_group(1)) + counting offsets kernel (one fewer
// launch) + fp16 g_y (less combine traffic).
// ============================================================================

#define HID   2048
#define INTER 1024
#define NEXP  8
#define MAXT  4096
#define MAXSLOTS (2 * MAXT)

typedef unsigned int u32;

// ---- device scratch ---------------------------------------------------------
__device__ int   g_cnt[NEXP];
__device__ int   g_off[NEXP];
__device__ int   g_fill[NEXP];
__device__ int   g_perm[MAXSLOTS];
__device__ float g_w[MAXSLOTS];
__device__ int   g_tidx[MAXT * 2];
__device__ float g_tw[MAXT * 2];
__device__ int   g_slot_of[MAXT * 2];

__device__ __half g_X16[(size_t)MAXT * HID];
__device__ __half g_Wg16[(size_t)NEXP * INTER * HID];
__device__ __half g_Wu16[(size_t)NEXP * INTER * HID];
__device__ __half g_Wd16[(size_t)NEXP * HID * INTER];
__device__ __half g_H16[(size_t)MAXSLOTS * INTER];
__device__ __half g_y16[(size_t)MAXSLOTS * HID];

// ---- PTX helpers (baseline sm_80-era only) -------------------------------------
__device__ __forceinline__ u32 smem_u32(const void* p) {
    u32 a;
    asm("{ .reg .u64 t; cvta.to.shared.u64 t, %1; cvt.u32.u64 %0, t; }" : "=r"(a) : "l"(p));
    return a;
}
__device__ __forceinline__ void cpa16(u32 dst, const void* src) {
    asm volatile("cp.async.cg.shared.global [%0], [%1], 16;" :: "r"(dst), "l"(src));
}
#define CPA_COMMIT() asm volatile("cp.async.commit_group;" ::: "memory")
#define CPA_WAIT1()  asm volatile("cp.async.wait_group 1;" ::: "memory")
#define CPA_WAIT0()  asm volatile("cp.async.wait_group 0;" ::: "memory")

__device__ __forceinline__ void ldsm4(u32* r, u32 addr) {
    asm volatile("ldmatrix.sync.aligned.m8n8.x4.shared.b16 {%0,%1,%2,%3}, [%4];"
                 : "=r"(r[0]), "=r"(r[1]), "=r"(r[2]), "=r"(r[3]) : "r"(addr));
}
__device__ __forceinline__ void mma16816(float* c, const u32* a, u32 b0, u32 b1) {
    asm volatile(
        "mma.sync.aligned.m16n8k16.row.col.f32.f16.f16.f32 "
        "{%0,%1,%2,%3}, {%4,%5,%6,%7}, {%8,%9}, {%0,%1,%2,%3};"
        : "+f"(c[0]), "+f"(c[1]), "+f"(c[2]), "+f"(c[3])
        : "r"(a[0]), "r"(a[1]), "r"(a[2]), "r"(a[3]), "r"(b0), "r"(b1));
}

// ---- smem geometry: BK=32 fp16 rows (64B data), pitch 80B ----------------------
#define PITCH 80
#define OFF_A  0              // 128 rows * 80 = 10240
#define OFF_B  10240          // 64 rows * 80 = 5120
#define STAGE_BYTES 15360
#define NSTAGE 3
#define SMEM_DYN (NSTAGE * STAGE_BYTES)   // 46080 -> 2 CTAs/SM

// ---- small kernels --------------------------------------------------------------
__global__ void router_kernel(const float* __restrict__ x,
                              const float* __restrict__ Wr,
                              float* __restrict__ logits_out, int write_logits) {
    const int t = blockIdx.x;
    const int warp = threadIdx.x >> 5;
    const int lane = threadIdx.x & 31;
    __shared__ float slog[NEXP];
    const float* xr = x + (size_t)t * HID;
    const float* wr = Wr + (size_t)warp * HID;
    float s = 0.0f;
    #pragma unroll 4
    for (int i = lane; i < HID; i += 32) s += xr[i] * wr[i];
    #pragma unroll
    for (int o = 16; o > 0; o >>= 1) s += __shfl_xor_sync(0xffffffffu, s, o);
    if (lane == 0) slog[warp] = s;
    __syncthreads();
    if (write_logits && threadIdx.x < NEXP)
        logits_out[t * NEXP + threadIdx.x] = slog[threadIdx.x];
    if (threadIdx.x == 0) {
        float v0 = -1e30f; int i0 = 0;
        #pragma unroll
        for (int i = 0; i < NEXP; i++) if (slog[i] > v0) { v0 = slog[i]; i0 = i; }
        float v1 = -1e30f; int i1 = 0;
        #pragma unroll
        for (int i = 0; i < NEXP; i++)
            if (i != i0 && slog[i] > v1) { v1 = slog[i]; i1 = i; }
        float ex = expf(v1 - v0);
        float inv = 1.0f / (1.0f + ex);
        g_tidx[2 * t] = i0; g_tidx[2 * t + 1] = i1;
        g_tw[2 * t] = inv;  g_tw[2 * t + 1] = ex * inv;
    }
}

// counting offsets: histogram g_tidx in one block; also zeroes g_fill
__global__ void offsets_kernel(int T) {
    __shared__ int hist[NEXP];
    if (threadIdx.x < NEXP) hist[threadIdx.x] = 0;
    __syncthreads();
    for (int i = threadIdx.x; i < 2 * T; i += blockDim.x)
        atomicAdd(&hist[g_tidx[i]], 1);
    __syncthreads();
    if (threadIdx.x == 0) {
        int o = 0;
        #pragma unroll
        for (int e = 0; e < NEXP; e++) {
            g_cnt[e] = hist[e];
            g_off[e] = o;
            g_fill[e] = 0;
            o += hist[e];
        }
    }
}

__global__ void scatter_kernel(int T) {
    int t = blockIdx.x * blockDim.x + threadIdx.x;
    if (t >= T) return;
    #pragma unroll
    for (int j = 0; j < 2; j++) {
        int e = g_tidx[2 * t + j];
        int p = atomicAdd(&g_fill[e], 1);
        int slot = g_off[e] + p;
        g_perm[slot] = t;
        g_w[slot] = g_tw[2 * t + j];
        g_slot_of[2 * t + j] = slot;
    }
}

// ---- conversion pre-pass: fp32 -> fp16 ------------------------------------------
__device__ __forceinline__ uint2 f4_to_h4(const float4 v) {
    __half2 a = __floats2half2_rn(v.x, v.y);
    __half2 b = __floats2half2_rn(v.z, v.w);
    return make_uint2(*(u32*)&a, *(u32*)&b);
}

__global__ void split_all_kernel(const float* __restrict__ x,
                                 const float* __restrict__ Wg,
                                 const float* __restrict__ Wu,
                                 const float* __restrict__ Wd, int nx, int nw) {
    int i = blockIdx.x * blockDim.x + threadIdx.x;
    if (i < nx) {
        ((uint2*)g_X16)[i] = f4_to_h4(((const float4*)x)[i]);
    } else if (i < nx + nw) {
        int j = i - nx;
        ((uint2*)g_Wg16)[j] = f4_to_h4(((const float4*)Wg)[j]);
    } else if (i < nx + 2 * nw) {
        int j = i - nx - nw;
        ((uint2*)g_Wu16)[j] = f4_to_h4(((const float4*)Wu)[j]);
    } else if (i < nx + 3 * nw) {
        int j = i - nx - 2 * nw;
        ((uint2*)g_Wd16)[j] = f4_to_h4(((const float4*)Wd)[j]);
    }
}

// ---- GEMM 1: gate+up. CTA: 128 slots x (32 gate + 32 up), warp tile 32x32 -------
__global__ __launch_bounds__(256, 2) void gateup_mma_kernel() {
    const int e   = blockIdx.z;
    const int cnt = g_cnt[e];
    const int m0  = blockIdx.y * 128;
    if (m0 >= cnt) return;
    const int rows = min(cnt - m0, 128);
    const int base = g_off[e] + m0;
    const int n0   = blockIdx.x * 32;

    extern __shared__ char dsm[];
    const u32 sm0 = smem_u32(dsm);

    const int tid  = threadIdx.x;
    const int lane = tid & 31;
    const int wid  = tid >> 5;
    const int wm   = wid >> 1;          // 0..3 -> 32-row band
    const int wn   = wid & 1;           // 0 = gate cols, 1 = up cols

    // ---- loader: 3 cp.async per thread per stage ----
    const int q = tid >> 2;             // 0..63
    const int c = tid & 3;
    const int r0 = min(q, rows - 1);
    const int r1 = min(q + 64, rows - 1);
    const size_t xo0 = (size_t)g_perm[base + r0] * HID + c * 8;
    const size_t xo1 = (size_t)g_perm[base + r1] * HID + c * 8;
    const __half* pb;
    if (q < 32) pb = g_Wg16 + ((size_t)e * INTER + n0 + q) * HID + c * 8;
    else        pb = g_Wu16 + ((size_t)e * INTER + n0 + (q - 32)) * HID + c * 8;

    const u32 dA0 = (u32)(OFF_A + q * PITCH + c * 16);
    const u32 dA1 = dA0 + 64 * PITCH;
    const u32 dB  = (u32)(OFF_B + q * PITCH + c * 16);

    // ---- ldmatrix bases: warp tile 32 rows x 32 B-rows ----
    const u32 a_off = (u32)((wm * 32 + (lane & 7) + ((lane >> 3) & 1) * 8) * PITCH
                    + (lane >> 4) * 16);
    const u32 b_off0 = (u32)((wn * 32 + (lane & 7) + (lane >> 4) * 8) * PITCH
                    + ((lane >> 3) & 1) * 16);
    const u32 b_off1 = b_off0 + 16 * PITCH;

    float acc[2][4][4];
    #pragma unroll
    for (int i = 0; i < 2; i++)
        #pragma unroll
        for (int j = 0; j < 4; j++)
            #pragma unroll
            for (int k = 0; k < 4; k++) acc[i][j][k] = 0.0f;

    const int KT = HID / 32;            // 64

    #pragma unroll
    for (int p = 0; p < NSTAGE - 1; p++) {
        const u32 sb = sm0 + (u32)p * STAGE_BYTES;
        const size_t ko = (size_t)p * 32;
        cpa16(sb + dA0, g_X16 + xo0 + ko);
        cpa16(sb + dA1, g_X16 + xo1 + ko);
        cpa16(sb + dB,  pb + ko);
        CPA_COMMIT();
    }

    #pragma unroll 1
    for (int kt = 0; kt < KT; kt++) {
        if (kt == KT - 1) CPA_WAIT0(); else CPA_WAIT1();
        __syncthreads();
        if (kt + NSTAGE - 1 < KT) {
            const u32 sb = sm0 + (u32)((kt + NSTAGE - 1) % NSTAGE) * STAGE_BYTES;
            const size_t ko = (size_t)(kt + NSTAGE - 1) * 32;
            cpa16(sb + dA0, g_X16 + xo0 + ko);
            cpa16(sb + dA1, g_X16 + xo1 + ko);
            cpa16(sb + dB,  pb + ko);
            CPA_COMMIT();
        }
        const u32 sb = sm0 + (u32)(kt % NSTAGE) * STAGE_BYTES;
        #pragma unroll
        for (int ks = 0; ks < 2; ks++) {
            u32 ah[2][4], bh[2][4];
            #pragma unroll
            for (int mi = 0; mi < 2; mi++)
                ldsm4(ah[mi], sb + OFF_A + a_off + (u32)(mi * 16 * PITCH) + (u32)(ks * 32));
            ldsm4(bh[0], sb + OFF_B + b_off0 + (u32)(ks * 32));
            ldsm4(bh[1], sb + OFF_B + b_off1 + (u32)(ks * 32));
            #pragma unroll
            for (int mi = 0; mi < 2; mi++) {
                #pragma unroll
                for (int ni = 0; ni < 4; ni++) {
                    const int g = ni >> 1, s = (ni & 1) * 2;
                    mma16816(acc[mi][ni], ah[mi], bh[g][s], bh[g][s + 1]);
                }
            }
        }
    }
    __syncthreads();

    // ---- epilogue: exchange via smem (128 x 72 f32), silu(g)*u, store fp16 ----
    float* S = (float*)dsm;
    #pragma unroll
    for (int mi = 0; mi < 2; mi++) {
        const int rr = wm * 32 + mi * 16 + (lane >> 2);
        #pragma unroll
        for (int ni = 0; ni < 4; ni++) {
            const int cc = wn * 32 + ni * 8 + 2 * (lane & 3);
            *(float2*)(S + (size_t)rr * 72 + cc)       = make_float2(acc[mi][ni][0], acc[mi][ni][1]);
            *(float2*)(S + (size_t)(rr + 8) * 72 + cc) = make_float2(acc[mi][ni][2], acc[mi][ni][3]);
        }
    }
    __syncthreads();
    {
        const int row  = tid >> 1;
        const int half = (tid & 1) * 16;
        if (row < rows) {
            u32 ph[8];
            #pragma unroll
            for (int p = 0; p < 8; p++) {
                float g0 = S[(size_t)row * 72 + half + 2 * p];
                float g1 = S[(size_t)row * 72 + half + 2 * p + 1];
                float u0 = S[(size_t)row * 72 + 32 + half + 2 * p];
                float u1 = S[(size_t)row * 72 + 32 + half + 2 * p + 1];
                float h0 = (g0 / (1.0f + expf(-g0))) * u0;
                float h1 = (g1 / (1.0f + expf(-g1))) * u1;
                __half2 A = __floats2half2_rn(h0, h1);
                ph[p] = *(u32*)&A;
            }
            u32* dh = (u32*)(g_H16 + (size_t)(base + row) * INTER + n0 + half);
            ((uint4*)dh)[0] = make_uint4(ph[0], ph[1], ph[2], ph[3]);
            ((uint4*)dh)[1] = make_uint4(ph[4], ph[5], ph[6], ph[7]);
        }
    }
}

// ---- GEMM 2: down. CTA: 128 slots x 64 hid, warp tile 32x32, K=1024 --------------
__global__ __launch_bounds__(256, 2) void down_mma_kernel() {
    const int e   = blockIdx.z;
    const int cnt = g_cnt[e];
    const int m0  = blockIdx.y * 128;
    if (m0 >= cnt) return;
    const int rows = min(cnt - m0, 128);
    const int base = g_off[e] + m0;
    const int n0   = blockIdx.x * 64;

    extern __shared__ char dsm[];
    const u32 sm0 = smem_u32(dsm);

    const int tid  = threadIdx.x;
    const int lane = tid & 31;
    const int wid  = tid >> 5;
    const int wm   = wid >> 1;
    const int wn   = wid & 1;

    const int q = tid >> 2;
    const int c = tid & 3;
    const int r0 = min(q, rows - 1);
    const int r1 = min(q + 64, rows - 1);
    const size_t ho0 = (size_t)(base + r0) * INTER + c * 8;
    const size_t ho1 = (size_t)(base + r1) * INTER + c * 8;
    const __half* pb = g_Wd16 + ((size_t)e * HID + n0 + q) * INTER + c * 8;

    const u32 dA0 = (u32)(OFF_A + q * PITCH + c * 16);
    const u32 dA1 = dA0 + 64 * PITCH;
    const u32 dB  = (u32)(OFF_B + q * PITCH + c * 16);

    const u32 a_off = (u32)((wm * 32 + (lane & 7) + ((lane >> 3) & 1) * 8) * PITCH
                    + (lane >> 4) * 16);
    const u32 b_off0 = (u32)((wn * 32 + (lane & 7) + (lane >> 4) * 8) * PITCH
                    + ((lane >> 3) & 1) * 16);
    const u32 b_off1 = b_off0 + 16 * PITCH;

    float acc[2][4][4];
    #pragma unroll
    for (int i = 0; i < 2; i++)
        #pragma unroll
        for (int j = 0; j < 4; j++)
            #pragma unroll
            for (int k = 0; k < 4; k++) acc[i][j][k] = 0.0f;

    const int KT = INTER / 32;          // 32

    #pragma unroll
    for (int p = 0; p < NSTAGE - 1; p++) {
        const u32 sb = sm0 + (u32)p * STAGE_BYTES;
        const size_t ko = (size_t)p * 32;
        cpa16(sb + dA0, g_H16 + ho0 + ko);
        cpa16(sb + dA1, g_H16 + ho1 + ko);
        cpa16(sb + dB,  pb + ko);
        CPA_COMMIT();
    }

    #pragma unroll 1
    for (int kt = 0; kt < KT; kt++) {
        if (kt == KT - 1) CPA_WAIT0(); else CPA_WAIT1();
        __syncthreads();
        if (kt + NSTAGE - 1 < KT) {
            const u32 sb = sm0 + (u32)((kt + NSTAGE - 1) % NSTAGE) * STAGE_BYTES;
            const size_t ko = (size_t)(kt + NSTAGE - 1) * 32;
            cpa16(sb + dA0, g_H16 + ho0 + ko);
            cpa16(sb + dA1, g_H16 + ho1 + ko);
            cpa16(sb + dB,  pb + ko);
            CPA_COMMIT();
        }
        const u32 sb = sm0 + (u32)(kt % NSTAGE) * STAGE_BYTES;
        #pragma unroll
        for (int ks = 0; ks < 2; ks++) {
            u32 ah[2][4], bh[2][4];
            #pragma unroll
            for (int mi = 0; mi < 2; mi++)
                ldsm4(ah[mi], sb + OFF_A + a_off + (u32)(mi * 16 * PITCH) + (u32)(ks * 32));
            ldsm4(bh[0], sb + OFF_B + b_off0 + (u32)(ks * 32));
            ldsm4(bh[1], sb + OFF_B + b_off1 + (u32)(ks * 32));
            #pragma unroll
            for (int mi = 0; mi < 2; mi++) {
                #pragma unroll
                for (int ni = 0; ni < 4; ni++) {
                    const int g = ni >> 1, s = (ni & 1) * 2;
                    mma16816(acc[mi][ni], ah[mi], bh[g][s], bh[g][s + 1]);
                }
            }
        }
    }

    // ---- epilogue: scale by routing weight, store fp16 ----
    #pragma unroll
    for (int mi = 0; mi < 2; mi++) {
        const int r0o = wm * 32 + mi * 16 + (lane >> 2);
        const int r1o = r0o + 8;
        const float w0 = (r0o < rows) ? g_w[base + r0o] : 0.0f;
        const float w1 = (r1o < rows) ? g_w[base + r1o] : 0.0f;
        #pragma unroll
        for (int ni = 0; ni < 4; ni++) {
            const int cc = n0 + wn * 32 + ni * 8 + 2 * (lane & 3);
            if (r0o < rows) {
                __half2 v = __floats2half2_rn(w0 * acc[mi][ni][0], w0 * acc[mi][ni][1]);
                *(__half2*)(g_y16 + (size_t)(base + r0o) * HID + cc) = v;
            }
            if (r1o < rows) {
                __half2 v = __floats2half2_rn(w1 * acc[mi][ni][2], w1 * acc[mi][ni][3]);
                *(__half2*)(g_y16 + (size_t)(base + r1o) * HID + cc) = v;
            }
        }
    }
}

// ---- combine: out[t] = y16[slot0] + y16[slot1] (fp32 out) -------------------------
__global__ void combine_kernel(float* __restrict__ out, int T) {
    const int gid = blockIdx.x * blockDim.x + threadIdx.x;
    const int per_tok = HID / 4;
    if (gid >= T * per_tok) return;
    const int t = gid / per_tok;
    const int c = gid - t * per_tok;
    const int s0 = g_slot_of[2 * t];
    const int s1 = g_slot_of[2 * t + 1];
    uint2 pa = ((const uint2*)(g_y16 + (size_t)s0 * HID))[c];
    uint2 pb = ((const uint2*)(g_y16 + (size_t)s1 * HID))[c];
    __half2 a0 = *(__half2*)&pa.x, a1 = *(__half2*)&pa.y;
    __half2 b0 = *(__half2*)&pb.x, b1 = *(__half2*)&pb.y;
    float4 r;
    r.x = __low2float(a0)  + __low2float(b0);
    r.y = __high2float(a0) + __high2float(b0);
    r.z = __low2float(a1)  + __low2float(b1);
    r.w = __high2float(a1) + __high2float(b1);
    ((float4*)(out + (size_t)t * HID))[c] = r;
}

// ---- launch -------------------------------------------------------------------------
extern "C" void kernel_launch(void* const* d_in, const int* in_sizes, int n_in,
                              void* d_out, int out_size) {
    if (n_in < 5) return;
    const float* x  = (const float*)d_in[0];
    const float* Wr = (const float*)d_in[1];
    const float* Wg = (const float*)d_in[2];
    const float* Wu = (const float*)d_in[3];
    const float* Wd = (const float*)d_in[4];
    float* out = (float*)d_out;

    int T = in_sizes[0] / HID;
    if (T > MAXT) T = MAXT;

    cudaFuncSetAttribute(gateup_mma_kernel, cudaFuncAttributeMaxDynamicSharedMemorySize, SMEM_DYN);
    cudaFuncSetAttribute(down_mma_kernel,   cudaFuncAttributeMaxDynamicSharedMemorySize, SMEM_DYN);

    const int write_logits = (out_size >= T * HID + T * NEXP);
    float* logits = out + (size_t)T * HID;

    router_kernel<<<T, 256>>>(x, Wr, logits, write_logits);
    offsets_kernel<<<1, 256>>>(T);
    scatter_kernel<<<(T + 255) / 256, 256>>>(T);

    const int nx = T * HID / 4;
    const int nw = NEXP * INTER * HID / 4;
    split_all_kernel<<<(nx + 3 * nw + 255) / 256, 256>>>(x, Wg, Wu, Wd, nx, nw);

    gateup_mma_kernel<<<dim3(INTER / 32, MAXSLOTS / 128, NEXP), 256, SMEM_DYN>>>();
    down_mma_kernel<<<dim3(HID / 64, MAXSLOTS / 128, NEXP), 256, SMEM_DYN>>>();

    combine_kernel<<<(T * (HID / 4) + 255) / 256, 256>>>(out, T);
}

// round 14
// speedup vs baseline: 1.2928x; 1.0184x over previous
#include <cuda_runtime.h>
#include <cuda_fp16.h>
#include <cstdint>

// ============================================================================
// BiBoSparseMoeBlock: top-2-of-8 MoE SwiGLU, fp32 in/out.
// Round 14: R10 champion GEMMs unchanged; combine pass eliminated — down
// epilogue atomicAdds its weighted tile directly into out (each element gets
// exactly 2 commutative fp32 contributions -> bitwise deterministic).
// ============================================================================

#define HID   2048
#define INTER 1024
#define NEXP  8
#define MAXT  4096
#define MAXSLOTS (2 * MAXT)

typedef unsigned int u32;

// ---- device scratch ---------------------------------------------------------
__device__ int   g_cnt[NEXP];
__device__ int   g_off[NEXP];
__device__ int   g_fill[NEXP];
__device__ int   g_perm[MAXSLOTS];
__device__ float g_w[MAXSLOTS];
__device__ int   g_tidx[MAXT * 2];
__device__ float g_tw[MAXT * 2];

__device__ __half g_X16[(size_t)MAXT * HID];
__device__ __half g_Wg16[(size_t)NEXP * INTER * HID];
__device__ __half g_Wu16[(size_t)NEXP * INTER * HID];
__device__ __half g_Wd16[(size_t)NEXP * HID * INTER];
__device__ __half g_H16[(size_t)MAXSLOTS * INTER];

// ---- PTX helpers (baseline sm_80-era only) -------------------------------------
__device__ __forceinline__ u32 smem_u32(const void* p) {
    u32 a;
    asm("{ .reg .u64 t; cvta.to.shared.u64 t, %1; cvt.u32.u64 %0, t; }" : "=r"(a) : "l"(p));
    return a;
}
__device__ __forceinline__ void cpa16(u32 dst, const void* src) {
    asm volatile("cp.async.cg.shared.global [%0], [%1], 16;" :: "r"(dst), "l"(src));
}
#define CPA_COMMIT() asm volatile("cp.async.commit_group;" ::: "memory")
#define CPA_WAIT1()  asm volatile("cp.async.wait_group 1;" ::: "memory")
#define CPA_WAIT0()  asm volatile("cp.async.wait_group 0;" ::: "memory")

__device__ __forceinline__ void ldsm4(u32* r, u32 addr) {
    asm volatile("ldmatrix.sync.aligned.m8n8.x4.shared.b16 {%0,%1,%2,%3}, [%4];"
                 : "=r"(r[0]), "=r"(r[1]), "=r"(r[2]), "=r"(r[3]) : "r"(addr));
}
__device__ __forceinline__ void mma16816(float* c, const u32* a, u32 b0, u32 b1) {
    asm volatile(
        "mma.sync.aligned.m16n8k16.row.col.f32.f16.f16.f32 "
        "{%0,%1,%2,%3}, {%4,%5,%6,%7}, {%8,%9}, {%0,%1,%2,%3};"
        : "+f"(c[0]), "+f"(c[1]), "+f"(c[2]), "+f"(c[3])
        : "r"(a[0]), "r"(a[1]), "r"(a[2]), "r"(a[3]), "r"(b0), "r"(b1));
}

// ---- smem geometry: BK=32 fp16 rows (64B data), pitch 80B ----------------------
#define PITCH 80
#define OFF_A  0              // 128 rows * 80 = 10240
#define OFF_B  10240          // 64 rows * 80 = 5120
#define STAGE_BYTES 15360
#define NSTAGE 3
#define SMEM_DYN (NSTAGE * STAGE_BYTES)   // 46080 -> 2 CTAs/SM

// ---- small kernels --------------------------------------------------------------
__global__ void router_kernel(const float* __restrict__ x,
                              const float* __restrict__ Wr,
                              float* __restrict__ logits_out, int write_logits) {
    const int t = blockIdx.x;
    const int warp = threadIdx.x >> 5;
    const int lane = threadIdx.x & 31;
    __shared__ float slog[NEXP];
    const float* xr = x + (size_t)t * HID;
    const float* wr = Wr + (size_t)warp * HID;
    float s = 0.0f;
    #pragma unroll 4
    for (int i = lane; i < HID; i += 32) s += xr[i] * wr[i];
    #pragma unroll
    for (int o = 16; o > 0; o >>= 1) s += __shfl_xor_sync(0xffffffffu, s, o);
    if (lane == 0) slog[warp] = s;
    __syncthreads();
    if (write_logits && threadIdx.x < NEXP)
        logits_out[t * NEXP + threadIdx.x] = slog[threadIdx.x];
    if (threadIdx.x == 0) {
        float v0 = -1e30f; int i0 = 0;
        #pragma unroll
        for (int i = 0; i < NEXP; i++) if (slog[i] > v0) { v0 = slog[i]; i0 = i; }
        float v1 = -1e30f; int i1 = 0;
        #pragma unroll
        for (int i = 0; i < NEXP; i++)
            if (i != i0 && slog[i] > v1) { v1 = slog[i]; i1 = i; }
        float ex = expf(v1 - v0);
        float inv = 1.0f / (1.0f + ex);
        g_tidx[2 * t] = i0; g_tidx[2 * t + 1] = i1;
        g_tw[2 * t] = inv;  g_tw[2 * t + 1] = ex * inv;
    }
}

// counting offsets: histogram g_tidx in one block; also zeroes g_fill
__global__ void offsets_kernel(int T) {
    __shared__ int hist[NEXP];
    if (threadIdx.x < NEXP) hist[threadIdx.x] = 0;
    __syncthreads();
    for (int i = threadIdx.x; i < 2 * T; i += blockDim.x)
        atomicAdd(&hist[g_tidx[i]], 1);
    __syncthreads();
    if (threadIdx.x == 0) {
        int o = 0;
        #pragma unroll
        for (int e = 0; e < NEXP; e++) {
            g_cnt[e] = hist[e];
            g_off[e] = o;
            g_fill[e] = 0;
            o += hist[e];
        }
    }
}

__global__ void scatter_kernel(int T) {
    int t = blockIdx.x * blockDim.x + threadIdx.x;
    if (t >= T) return;
    #pragma unroll
    for (int j = 0; j < 2; j++) {
        int e = g_tidx[2 * t + j];
        int p = atomicAdd(&g_fill[e], 1);
        int slot = g_off[e] + p;
        g_perm[slot] = t;
        g_w[slot] = g_tw[2 * t + j];
    }
}

// ---- conversion pre-pass: fp32 -> fp16 ------------------------------------------
__device__ __forceinline__ uint2 f4_to_h4(const float4 v) {
    __half2 a = __floats2half2_rn(v.x, v.y);
    __half2 b = __floats2half2_rn(v.z, v.w);
    return make_uint2(*(u32*)&a, *(u32*)&b);
}

__global__ void split_all_kernel(const float* __restrict__ x,
                                 const float* __restrict__ Wg,
                                 const float* __restrict__ Wu,
                                 const float* __restrict__ Wd, int nx, int nw) {
    int i = blockIdx.x * blockDim.x + threadIdx.x;
    if (i < nx) {
        ((uint2*)g_X16)[i] = f4_to_h4(((const float4*)x)[i]);
    } else if (i < nx + nw) {
        int j = i - nx;
        ((uint2*)g_Wg16)[j] = f4_to_h4(((const float4*)Wg)[j]);
    } else if (i < nx + 2 * nw) {
        int j = i - nx - nw;
        ((uint2*)g_Wu16)[j] = f4_to_h4(((const float4*)Wu)[j]);
    } else if (i < nx + 3 * nw) {
        int j = i - nx - 2 * nw;
        ((uint2*)g_Wd16)[j] = f4_to_h4(((const float4*)Wd)[j]);
    }
}

// ---- GEMM 1: gate+up. CTA: 128 slots x (32 gate + 32 up), warp tile 32x32 -------
__global__ __launch_bounds__(256, 2) void gateup_mma_kernel() {
    const int e   = blockIdx.z;
    const int cnt = g_cnt[e];
    const int m0  = blockIdx.y * 128;
    if (m0 >= cnt) return;
    const int rows = min(cnt - m0, 128);
    const int base = g_off[e] + m0;
    const int n0   = blockIdx.x * 32;

    extern __shared__ char dsm[];
    const u32 sm0 = smem_u32(dsm);

    const int tid  = threadIdx.x;
    const int lane = tid & 31;
    const int wid  = tid >> 5;
    const int wm   = wid >> 1;          // 0..3 -> 32-row band
    const int wn   = wid & 1;           // 0 = gate cols, 1 = up cols

    // ---- loader: 3 cp.async per thread per stage ----
    const int q = tid >> 2;             // 0..63
    const int c = tid & 3;
    const int r0 = min(q, rows - 1);
    const int r1 = min(q + 64, rows - 1);
    const size_t xo0 = (size_t)g_perm[base + r0] * HID + c * 8;
    const size_t xo1 = (size_t)g_perm[base + r1] * HID + c * 8;
    const __half* pb;
    if (q < 32) pb = g_Wg16 + ((size_t)e * INTER + n0 + q) * HID + c * 8;
    else        pb = g_Wu16 + ((size_t)e * INTER + n0 + (q - 32)) * HID + c * 8;

    const u32 dA0 = (u32)(OFF_A + q * PITCH + c * 16);
    const u32 dA1 = dA0 + 64 * PITCH;
    const u32 dB  = (u32)(OFF_B + q * PITCH + c * 16);

    // ---- ldmatrix bases: warp tile 32 rows x 32 B-rows ----
    const u32 a_off = (u32)((wm * 32 + (lane & 7) + ((lane >> 3) & 1) * 8) * PITCH
                    + (lane >> 4) * 16);
    const u32 b_off0 = (u32)((wn * 32 + (lane & 7) + (lane >> 4) * 8) * PITCH
                    + ((lane >> 3) & 1) * 16);
    const u32 b_off1 = b_off0 + 16 * PITCH;

    float acc[2][4][4];
    #pragma unroll
    for (int i = 0; i < 2; i++)
        #pragma unroll
        for (int j = 0; j < 4; j++)
            #pragma unroll
            for (int k = 0; k < 4; k++) acc[i][j][k] = 0.0f;

    const int KT = HID / 32;            // 64

    #pragma unroll
    for (int p = 0; p < NSTAGE - 1; p++) {
        const u32 sb = sm0 + (u32)p * STAGE_BYTES;
        const size_t ko = (size_t)p * 32;
        cpa16(sb + dA0, g_X16 + xo0 + ko);
        cpa16(sb + dA1, g_X16 + xo1 + ko);
        cpa16(sb + dB,  pb + ko);
        CPA_COMMIT();
    }

    #pragma unroll 1
    for (int kt = 0; kt < KT; kt++) {
        if (kt == KT - 1) CPA_WAIT0(); else CPA_WAIT1();
        __syncthreads();
        if (kt + NSTAGE - 1 < KT) {
            const u32 sb = sm0 + (u32)((kt + NSTAGE - 1) % NSTAGE) * STAGE_BYTES;
            const size_t ko = (size_t)(kt + NSTAGE - 1) * 32;
            cpa16(sb + dA0, g_X16 + xo0 + ko);
            cpa16(sb + dA1, g_X16 + xo1 + ko);
            cpa16(sb + dB,  pb + ko);
            CPA_COMMIT();
        }
        const u32 sb = sm0 + (u32)(kt % NSTAGE) * STAGE_BYTES;
        #pragma unroll
        for (int ks = 0; ks < 2; ks++) {
            u32 ah[2][4], bh[2][4];
            #pragma unroll
            for (int mi = 0; mi < 2; mi++)
                ldsm4(ah[mi], sb + OFF_A + a_off + (u32)(mi * 16 * PITCH) + (u32)(ks * 32));
            ldsm4(bh[0], sb + OFF_B + b_off0 + (u32)(ks * 32));
            ldsm4(bh[1], sb + OFF_B + b_off1 + (u32)(ks * 32));
            #pragma unroll
            for (int mi = 0; mi < 2; mi++) {
                #pragma unroll
                for (int ni = 0; ni < 4; ni++) {
                    const int g = ni >> 1, s = (ni & 1) * 2;
                    mma16816(acc[mi][ni], ah[mi], bh[g][s], bh[g][s + 1]);
                }
            }
        }
    }
    __syncthreads();

    // ---- epilogue: exchange via smem (128 x 72 f32), silu(g)*u, store fp16 ----
    float* S = (float*)dsm;
    #pragma unroll
    for (int mi = 0; mi < 2; mi++) {
        const int rr = wm * 32 + mi * 16 + (lane >> 2);
        #pragma unroll
        for (int ni = 0; ni < 4; ni++) {
            const int cc = wn * 32 + ni * 8 + 2 * (lane & 3);
            *(float2*)(S + (size_t)rr * 72 + cc)       = make_float2(acc[mi][ni][0], acc[mi][ni][1]);
            *(float2*)(S + (size_t)(rr + 8) * 72 + cc) = make_float2(acc[mi][ni][2], acc[mi][ni][3]);
        }
    }
    __syncthreads();
    {
        const int row  = tid >> 1;
        const int half = (tid & 1) * 16;
        if (row < rows) {
            u32 ph[8];
            #pragma unroll
            for (int p = 0; p < 8; p++) {
                float g0 = S[(size_t)row * 72 + half + 2 * p];
                float g1 = S[(size_t)row * 72 + half + 2 * p + 1];
                float u0 = S[(size_t)row * 72 + 32 + half + 2 * p];
                float u1 = S[(size_t)row * 72 + 32 + half + 2 * p + 1];
                float h0 = (g0 / (1.0f + expf(-g0))) * u0;
                float h1 = (g1 / (1.0f + expf(-g1))) * u1;
                __half2 A = __floats2half2_rn(h0, h1);
                ph[p] = *(u32*)&A;
            }
            u32* dh = (u32*)(g_H16 + (size_t)(base + row) * INTER + n0 + half);
            ((uint4*)dh)[0] = make_uint4(ph[0], ph[1], ph[2], ph[3]);
            ((uint4*)dh)[1] = make_uint4(ph[4], ph[5], ph[6], ph[7]);
        }
    }
}

// ---- GEMM 2: down. CTA: 128 slots x 64 hid, warp tile 32x32, K=1024 --------------
// Epilogue atomicAdds weighted results directly into out (2 contribs/element).
__global__ __launch_bounds__(256, 2) void down_mma_kernel(float* __restrict__ out) {
    const int e   = blockIdx.z;
    const int cnt = g_cnt[e];
    const int m0  = blockIdx.y * 128;
    if (m0 >= cnt) return;
    const int rows = min(cnt - m0, 128);
    const int base = g_off[e] + m0;
    const int n0   = blockIdx.x * 64;

    extern __shared__ char dsm[];
    const u32 sm0 = smem_u32(dsm);

    const int tid  = threadIdx.x;
    const int lane = tid & 31;
    const int wid  = tid >> 5;
    const int wm   = wid >> 1;
    const int wn   = wid & 1;

    const int q = tid >> 2;
    const int c = tid & 3;
    const int r0 = min(q, rows - 1);
    const int r1 = min(q + 64, rows - 1);
    const size_t ho0 = (size_t)(base + r0) * INTER + c * 8;
    const size_t ho1 = (size_t)(base + r1) * INTER + c * 8;
    const __half* pb = g_Wd16 + ((size_t)e * HID + n0 + q) * INTER + c * 8;

    const u32 dA0 = (u32)(OFF_A + q * PITCH + c * 16);
    const u32 dA1 = dA0 + 64 * PITCH;
    const u32 dB  = (u32)(OFF_B + q * PITCH + c * 16);

    const u32 a_off = (u32)((wm * 32 + (lane & 7) + ((lane >> 3) & 1) * 8) * PITCH
                    + (lane >> 4) * 16);
    const u32 b_off0 = (u32)((wn * 32 + (lane & 7) + (lane >> 4) * 8) * PITCH
                    + ((lane >> 3) & 1) * 16);
    const u32 b_off1 = b_off0 + 16 * PITCH;

    float acc[2][4][4];
    #pragma unroll
    for (int i = 0; i < 2; i++)
        #pragma unroll
        for (int j = 0; j < 4; j++)
            #pragma unroll
            for (int k = 0; k < 4; k++) acc[i][j][k] = 0.0f;

    const int KT = INTER / 32;          // 32

    #pragma unroll
    for (int p = 0; p < NSTAGE - 1; p++) {
        const u32 sb = sm0 + (u32)p * STAGE_BYTES;
        const size_t ko = (size_t)p * 32;
        cpa16(sb + dA0, g_H16 + ho0 + ko);
        cpa16(sb + dA1, g_H16 + ho1 + ko);
        cpa16(sb + dB,  pb + ko);
        CPA_COMMIT();
    }

    #pragma unroll 1
    for (int kt = 0; kt < KT; kt++) {
        if (kt == KT - 1) CPA_WAIT0(); else CPA_WAIT1();
        __syncthreads();
        if (kt + NSTAGE - 1 < KT) {
            const u32 sb = sm0 + (u32)((kt + NSTAGE - 1) % NSTAGE) * STAGE_BYTES;
            const size_t ko = (size_t)(kt + NSTAGE - 1) * 32;
            cpa16(sb + dA0, g_H16 + ho0 + ko);
            cpa16(sb + dA1, g_H16 + ho1 + ko);
            cpa16(sb + dB,  pb + ko);
            CPA_COMMIT();
        }
        const u32 sb = sm0 + (u32)(kt % NSTAGE) * STAGE_BYTES;
        #pragma unroll
        for (int ks = 0; ks < 2; ks++) {
            u32 ah[2][4], bh[2][4];
            #pragma unroll
            for (int mi = 0; mi < 2; mi++)
                ldsm4(ah[mi], sb + OFF_A + a_off + (u32)(mi * 16 * PITCH) + (u32)(ks * 32));
            ldsm4(bh[0], sb + OFF_B + b_off0 + (u32)(ks * 32));
            ldsm4(bh[1], sb + OFF_B + b_off1 + (u32)(ks * 32));
            #pragma unroll
            for (int mi = 0; mi < 2; mi++) {
                #pragma unroll
                for (int ni = 0; ni < 4; ni++) {
                    const int g = ni >> 1, s = (ni & 1) * 2;
                    mma16816(acc[mi][ni], ah[mi], bh[g][s], bh[g][s + 1]);
                }
            }
        }
    }

    // ---- epilogue: scale by routing weight, atomicAdd into out ----
    #pragma unroll
    for (int mi = 0; mi < 2; mi++) {
        const int r0o = wm * 32 + mi * 16 + (lane >> 2);
        const int r1o = r0o + 8;
        if (r0o < rows) {
            const float w0 = g_w[base + r0o];
            float* dst0 = out + (size_t)g_perm[base + r0o] * HID;
            #pragma unroll
            for (int ni = 0; ni < 4; ni++) {
                const int cc = n0 + wn * 32 + ni * 8 + 2 * (lane & 3);
                atomicAdd(dst0 + cc,     w0 * acc[mi][ni][0]);
                atomicAdd(dst0 + cc + 1, w0 * acc[mi][ni][1]);
            }
        }
        if (r1o < rows) {
            const float w1 = g_w[base + r1o];
            float* dst1 = out + (size_t)g_perm[base + r1o] * HID;
            #pragma unroll
            for (int ni = 0; ni < 4; ni++) {
                const int cc = n0 + wn * 32 + ni * 8 + 2 * (lane & 3);
                atomicAdd(dst1 + cc,     w1 * acc[mi][ni][2]);
                atomicAdd(dst1 + cc + 1, w1 * acc[mi][ni][3]);
            }
        }
    }
}

// ---- launch -------------------------------------------------------------------------
extern "C" void kernel_launch(void* const* d_in, const int* in_sizes, int n_in,
                              void* d_out, int out_size) {
    if (n_in < 5) return;
    const float* x  = (const float*)d_in[0];
    const float* Wr = (const float*)d_in[1];
    const float* Wg = (const float*)d_in[2];
    const float* Wu = (const float*)d_in[3];
    const float* Wd = (const float*)d_in[4];
    float* out = (float*)d_out;

    int T = in_sizes[0] / HID;
    if (T > MAXT) T = MAXT;

    cudaFuncSetAttribute(gateup_mma_kernel, cudaFuncAttributeMaxDynamicSharedMemorySize, SMEM_DYN);
    cudaFuncSetAttribute(down_mma_kernel,   cudaFuncAttributeMaxDynamicSharedMemorySize, SMEM_DYN);

    const int write_logits = (out_size >= T * HID + T * NEXP);
    float* logits = out + (size_t)T * HID;

    // zero the token-output region (accumulated via atomicAdd by down kernel)
    cudaMemsetAsync(out, 0, (size_t)T * HID * sizeof(float));

    router_kernel<<<T, 256>>>(x, Wr, logits, write_logits);
    offsets_kernel<<<1, 256>>>(T);
    scatter_kernel<<<(T + 255) / 256, 256>>>(T);

    const int nx = T * HID / 4;
    const int nw = NEXP * INTER * HID / 4;
    split_all_kernel<<<(nx + 3 * nw + 255) / 256, 256>>>(x, Wg, Wu, Wd, nx, nw);

    gateup_mma_kernel<<<dim3(INTER / 32, MAXSLOTS / 128, NEXP), 256, SMEM_DYN>>>();
    down_mma_kernel<<<dim3(HID / 64, MAXSLOTS / 128, NEXP), 256, SMEM_DYN>>>(out);
}

// round 16
// speedup vs baseline: 1.3092x; 1.0127x over previous
#include <cuda_runtime.h>
#include <cuda_fp16.h>
#include <cstdint>

// ============================================================================
// BiBoSparseMoeBlock: top-2-of-8 MoE SwiGLU, fp32 in/out.
// Round 16: R14 structure (single stream, memset + atomic combine, champion
// GEMMs: warp 32x32, CTA 128x64, BK=32, 256 thr, 2 CTA/SM, 3-stage WAIT1)
// + router smem staging (kills the 8x re-read of each token row).
// ============================================================================

#define HID   2048
#define INTER 1024
#define NEXP  8
#define MAXT  4096
#define MAXSLOTS (2 * MAXT)

typedef unsigned int u32;

// ---- device scratch ---------------------------------------------------------
__device__ int   g_cnt[NEXP];
__device__ int   g_off[NEXP];
__device__ int   g_fill[NEXP];
__device__ int   g_perm[MAXSLOTS];
__device__ float g_w[MAXSLOTS];
__device__ int   g_tidx[MAXT * 2];
__device__ float g_tw[MAXT * 2];

__device__ __half g_X16[(size_t)MAXT * HID];
__device__ __half g_Wg16[(size_t)NEXP * INTER * HID];
__device__ __half g_Wu16[(size_t)NEXP * INTER * HID];
__device__ __half g_Wd16[(size_t)NEXP * HID * INTER];
__device__ __half g_H16[(size_t)MAXSLOTS * INTER];

// ---- PTX helpers (baseline sm_80-era only) -------------------------------------
__device__ __forceinline__ u32 smem_u32(const void* p) {
    u32 a;
    asm("{ .reg .u64 t; cvta.to.shared.u64 t, %1; cvt.u32.u64 %0, t; }" : "=r"(a) : "l"(p));
    return a;
}
__device__ __forceinline__ void cpa16(u32 dst, const void* src) {
    asm volatile("cp.async.cg.shared.global [%0], [%1], 16;" :: "r"(dst), "l"(src));
}
#define CPA_COMMIT() asm volatile("cp.async.commit_group;" ::: "memory")
#define CPA_WAIT1()  asm volatile("cp.async.wait_group 1;" ::: "memory")
#define CPA_WAIT0()  asm volatile("cp.async.wait_group 0;" ::: "memory")

__device__ __forceinline__ void ldsm4(u32* r, u32 addr) {
    asm volatile("ldmatrix.sync.aligned.m8n8.x4.shared.b16 {%0,%1,%2,%3}, [%4];"
                 : "=r"(r[0]), "=r"(r[1]), "=r"(r[2]), "=r"(r[3]) : "r"(addr));
}
__device__ __forceinline__ void mma16816(float* c, const u32* a, u32 b0, u32 b1) {
    asm volatile(
        "mma.sync.aligned.m16n8k16.row.col.f32.f16.f16.f32 "
        "{%0,%1,%2,%3}, {%4,%5,%6,%7}, {%8,%9}, {%0,%1,%2,%3};"
        : "+f"(c[0]), "+f"(c[1]), "+f"(c[2]), "+f"(c[3])
        : "r"(a[0]), "r"(a[1]), "r"(a[2]), "r"(a[3]), "r"(b0), "r"(b1));
}

// ---- smem geometry: BK=32 fp16 rows (64B data), pitch 80B ----------------------
#define PITCH 80
#define OFF_A  0              // 128 rows * 80 = 10240
#define OFF_B  10240          // 64 rows * 80 = 5120
#define STAGE_BYTES 15360
#define NSTAGE 3
#define SMEM_DYN (NSTAGE * STAGE_BYTES)   // 46080 -> 2 CTAs/SM

// ---- small kernels --------------------------------------------------------------
__global__ void router_kernel(const float* __restrict__ x,
                              const float* __restrict__ Wr,
                              float* __restrict__ logits_out, int write_logits) {
    const int t = blockIdx.x;
    const int warp = threadIdx.x >> 5;
    const int lane = threadIdx.x & 31;
    __shared__ float xs[HID];           // 8 KB: stage the token row ONCE
    __shared__ float slog[NEXP];

    const float4* xr = (const float4*)(x + (size_t)t * HID);
    for (int i = threadIdx.x; i < HID / 4; i += 256)
        ((float4*)xs)[i] = xr[i];
    __syncthreads();

    const float* wr = Wr + (size_t)warp * HID;
    float s = 0.0f;
    #pragma unroll 4
    for (int i = lane; i < HID; i += 32) s += xs[i] * wr[i];
    #pragma unroll
    for (int o = 16; o > 0; o >>= 1) s += __shfl_xor_sync(0xffffffffu, s, o);
    if (lane == 0) slog[warp] = s;
    __syncthreads();
    if (write_logits && threadIdx.x < NEXP)
        logits_out[t * NEXP + threadIdx.x] = slog[threadIdx.x];
    if (threadIdx.x == 0) {
        float v0 = -1e30f; int i0 = 0;
        #pragma unroll
        for (int i = 0; i < NEXP; i++) if (slog[i] > v0) { v0 = slog[i]; i0 = i; }
        float v1 = -1e30f; int i1 = 0;
        #pragma unroll
        for (int i = 0; i < NEXP; i++)
            if (i != i0 && slog[i] > v1) { v1 = slog[i]; i1 = i; }
        float ex = expf(v1 - v0);
        float inv = 1.0f / (1.0f + ex);
        g_tidx[2 * t] = i0; g_tidx[2 * t + 1] = i1;
        g_tw[2 * t] = inv;  g_tw[2 * t + 1] = ex * inv;
    }
}

// counting offsets: histogram g_tidx in one block; also zeroes g_fill
__global__ void offsets_kernel(int T) {
    __shared__ int hist[NEXP];
    if (threadIdx.x < NEXP) hist[threadIdx.x] = 0;
    __syncthreads();
    for (int i = threadIdx.x; i < 2 * T; i += blockDim.x)
        atomicAdd(&hist[g_tidx[i]], 1);
    __syncthreads();
    if (threadIdx.x == 0) {
        int o = 0;
        #pragma unroll
        for (int e = 0; e < NEXP; e++) {
            g_cnt[e] = hist[e];
            g_off[e] = o;
            g_fill[e] = 0;
            o += hist[e];
        }
    }
}

__global__ void scatter_kernel(int T) {
    int t = blockIdx.x * blockDim.x + threadIdx.x;
    if (t >= T) return;
    #pragma unroll
    for (int j = 0; j < 2; j++) {
        int e = g_tidx[2 * t + j];
        int p = atomicAdd(&g_fill[e], 1);
        int slot = g_off[e] + p;
        g_perm[slot] = t;
        g_w[slot] = g_tw[2 * t + j];
    }
}

// ---- conversion pre-pass: fp32 -> fp16 ------------------------------------------
__device__ __forceinline__ uint2 f4_to_h4(const float4 v) {
    __half2 a = __floats2half2_rn(v.x, v.y);
    __half2 b = __floats2half2_rn(v.z, v.w);
    return make_uint2(*(u32*)&a, *(u32*)&b);
}

__global__ void split_all_kernel(const float* __restrict__ x,
                                 const float* __restrict__ Wg,
                                 const float* __restrict__ Wu,
                                 const float* __restrict__ Wd, int nx, int nw) {
    int i = blockIdx.x * blockDim.x + threadIdx.x;
    if (i < nx) {
        ((uint2*)g_X16)[i] = f4_to_h4(((const float4*)x)[i]);
    } else if (i < nx + nw) {
        int j = i - nx;
        ((uint2*)g_Wg16)[j] = f4_to_h4(((const float4*)Wg)[j]);
    } else if (i < nx + 2 * nw) {
        int j = i - nx - nw;
        ((uint2*)g_Wu16)[j] = f4_to_h4(((const float4*)Wu)[j]);
    } else if (i < nx + 3 * nw) {
        int j = i - nx - 2 * nw;
        ((uint2*)g_Wd16)[j] = f4_to_h4(((const float4*)Wd)[j]);
    }
}

// ---- GEMM 1: gate+up. CTA: 128 slots x (32 gate + 32 up), warp tile 32x32 -------
__global__ __launch_bounds__(256, 2) void gateup_mma_kernel() {
    const int e   = blockIdx.z;
    const int cnt = g_cnt[e];
    const int m0  = blockIdx.y * 128;
    if (m0 >= cnt) return;
    const int rows = min(cnt - m0, 128);
    const int base = g_off[e] + m0;
    const int n0   = blockIdx.x * 32;

    extern __shared__ char dsm[];
    const u32 sm0 = smem_u32(dsm);

    const int tid  = threadIdx.x;
    const int lane = tid & 31;
    const int wid  = tid >> 5;
    const int wm   = wid >> 1;          // 0..3 -> 32-row band
    const int wn   = wid & 1;           // 0 = gate cols, 1 = up cols

    // ---- loader: 3 cp.async per thread per stage ----
    const int q = tid >> 2;             // 0..63
    const int c = tid & 3;
    const int r0 = min(q, rows - 1);
    const int r1 = min(q + 64, rows - 1);
    const size_t xo0 = (size_t)g_perm[base + r0] * HID + c * 8;
    const size_t xo1 = (size_t)g_perm[base + r1] * HID + c * 8;
    const __half* pb;
    if (q < 32) pb = g_Wg16 + ((size_t)e * INTER + n0 + q) * HID + c * 8;
    else        pb = g_Wu16 + ((size_t)e * INTER + n0 + (q - 32)) * HID + c * 8;

    const u32 dA0 = (u32)(OFF_A + q * PITCH + c * 16);
    const u32 dA1 = dA0 + 64 * PITCH;
    const u32 dB  = (u32)(OFF_B + q * PITCH + c * 16);

    // ---- ldmatrix bases: warp tile 32 rows x 32 B-rows ----
    const u32 a_off = (u32)((wm * 32 + (lane & 7) + ((lane >> 3) & 1) * 8) * PITCH
                    + (lane >> 4) * 16);
    const u32 b_off0 = (u32)((wn * 32 + (lane & 7) + (lane >> 4) * 8) * PITCH
                    + ((lane >> 3) & 1) * 16);
    const u32 b_off1 = b_off0 + 16 * PITCH;

    float acc[2][4][4];
    #pragma unroll
    for (int i = 0; i < 2; i++)
        #pragma unroll
        for (int j = 0; j < 4; j++)
            #pragma unroll
            for (int k = 0; k < 4; k++) acc[i][j][k] = 0.0f;

    const int KT = HID / 32;            // 64

    #pragma unroll
    for (int p = 0; p < NSTAGE - 1; p++) {
        const u32 sb = sm0 + (u32)p * STAGE_BYTES;
        const size_t ko = (size_t)p * 32;
        cpa16(sb + dA0, g_X16 + xo0 + ko);
        cpa16(sb + dA1, g_X16 + xo1 + ko);
        cpa16(sb + dB,  pb + ko);
        CPA_COMMIT();
    }

    #pragma unroll 1
    for (int kt = 0; kt < KT; kt++) {
        if (kt == KT - 1) CPA_WAIT0(); else CPA_WAIT1();
        __syncthreads();
        if (kt + NSTAGE - 1 < KT) {
            const u32 sb = sm0 + (u32)((kt + NSTAGE - 1) % NSTAGE) * STAGE_BYTES;
            const size_t ko = (size_t)(kt + NSTAGE - 1) * 32;
            cpa16(sb + dA0, g_X16 + xo0 + ko);
            cpa16(sb + dA1, g_X16 + xo1 + ko);
            cpa16(sb + dB,  pb + ko);
            CPA_COMMIT();
        }
        const u32 sb = sm0 + (u32)(kt % NSTAGE) * STAGE_BYTES;
        #pragma unroll
        for (int ks = 0; ks < 2; ks++) {
            u32 ah[2][4], bh[2][4];
            #pragma unroll
            for (int mi = 0; mi < 2; mi++)
                ldsm4(ah[mi], sb + OFF_A + a_off + (u32)(mi * 16 * PITCH) + (u32)(ks * 32));
            ldsm4(bh[0], sb + OFF_B + b_off0 + (u32)(ks * 32));
            ldsm4(bh[1], sb + OFF_B + b_off1 + (u32)(ks * 32));
            #pragma unroll
            for (int mi = 0; mi < 2; mi++) {
                #pragma unroll
                for (int ni = 0; ni < 4; ni++) {
                    const int g = ni >> 1, s = (ni & 1) * 2;
                    mma16816(acc[mi][ni], ah[mi], bh[g][s], bh[g][s + 1]);
                }
            }
        }
    }
    __syncthreads();

    // ---- epilogue: exchange via smem (128 x 72 f32), silu(g)*u, store fp16 ----
    float* S = (float*)dsm;
    #pragma unroll
    for (int mi = 0; mi < 2; mi++) {
        const int rr = wm * 32 + mi * 16 + (lane >> 2);
        #pragma unroll
        for (int ni = 0; ni < 4; ni++) {
            const int cc = wn * 32 + ni * 8 + 2 * (lane & 3);
            *(float2*)(S + (size_t)rr * 72 + cc)       = make_float2(acc[mi][ni][0], acc[mi][ni][1]);
            *(float2*)(S + (size_t)(rr + 8) * 72 + cc) = make_float2(acc[mi][ni][2], acc[mi][ni][3]);
        }
    }
    __syncthreads();
    {
        const int row  = tid >> 1;
        const int half = (tid & 1) * 16;
        if (row < rows) {
            u32 ph[8];
            #pragma unroll
            for (int p = 0; p < 8; p++) {
                float g0 = S[(size_t)row * 72 + half + 2 * p];
                float g1 = S[(size_t)row * 72 + half + 2 * p + 1];
                float u0 = S[(size_t)row * 72 + 32 + half + 2 * p];
                float u1 = S[(size_t)row * 72 + 32 + half + 2 * p + 1];
                float h0 = (g0 / (1.0f + expf(-g0))) * u0;
                float h1 = (g1 / (1.0f + expf(-g1))) * u1;
                __half2 A = __floats2half2_rn(h0, h1);
                ph[p] = *(u32*)&A;
            }
            u32* dh = (u32*)(g_H16 + (size_t)(base + row) * INTER + n0 + half);
            ((uint4*)dh)[0] = make_uint4(ph[0], ph[1], ph[2], ph[3]);
            ((uint4*)dh)[1] = make_uint4(ph[4], ph[5], ph[6], ph[7]);
        }
    }
}

// ---- GEMM 2: down. CTA: 128 slots x 64 hid, warp tile 32x32, K=1024 --------------
// Epilogue atomicAdds weighted results directly into out (2 contribs/element).
__global__ __launch_bounds__(256, 2) void down_mma_kernel(float* __restrict__ out) {
    const int e   = blockIdx.z;
    const int cnt = g_cnt[e];
    const int m0  = blockIdx.y * 128;
    if (m0 >= cnt) return;
    const int rows = min(cnt - m0, 128);
    const int base = g_off[e] + m0;
    const int n0   = blockIdx.x * 64;

    extern __shared__ char dsm[];
    const u32 sm0 = smem_u32(dsm);

    const int tid  = threadIdx.x;
    const int lane = tid & 31;
    const int wid  = tid >> 5;
    const int wm   = wid >> 1;
    const int wn   = wid & 1;

    const int q = tid >> 2;
    const int c = tid & 3;
    const int r0 = min(q, rows - 1);
    const int r1 = min(q + 64, rows - 1);
    const size_t ho0 = (size_t)(base + r0) * INTER + c * 8;
    const size_t ho1 = (size_t)(base + r1) * INTER + c * 8;
    const __half* pb = g_Wd16 + ((size_t)e * HID + n0 + q) * INTER + c * 8;

    const u32 dA0 = (u32)(OFF_A + q * PITCH + c * 16);
    const u32 dA1 = dA0 + 64 * PITCH;
    const u32 dB  = (u32)(OFF_B + q * PITCH + c * 16);

    const u32 a_off = (u32)((wm * 32 + (lane & 7) + ((lane >> 3) & 1) * 8) * PITCH
                    + (lane >> 4) * 16);
    const u32 b_off0 = (u32)((wn * 32 + (lane & 7) + (lane >> 4) * 8) * PITCH
                    + ((lane >> 3) & 1) * 16);
    const u32 b_off1 = b_off0 + 16 * PITCH;

    float acc[2][4][4];
    #pragma unroll
    for (int i = 0; i < 2; i++)
        #pragma unroll
        for (int j = 0; j < 4; j++)
            #pragma unroll
            for (int k = 0; k < 4; k++) acc[i][j][k] = 0.0f;

    const int KT = INTER / 32;          // 32

    #pragma unroll
    for (int p = 0; p < NSTAGE - 1; p++) {
        const u32 sb = sm0 + (u32)p * STAGE_BYTES;
        const size_t ko = (size_t)p * 32;
        cpa16(sb + dA0, g_H16 + ho0 + ko);
        cpa16(sb + dA1, g_H16 + ho1 + ko);
        cpa16(sb + dB,  pb + ko);
        CPA_COMMIT();
    }

    #pragma unroll 1
    for (int kt = 0; kt < KT; kt++) {
        if (kt == KT - 1) CPA_WAIT0(); else CPA_WAIT1();
        __syncthreads();
        if (kt + NSTAGE - 1 < KT) {
            const u32 sb = sm0 + (u32)((kt + NSTAGE - 1) % NSTAGE) * STAGE_BYTES;
            const size_t ko = (size_t)(kt + NSTAGE - 1) * 32;
            cpa16(sb + dA0, g_H16 + ho0 + ko);
            cpa16(sb + dA1, g_H16 + ho1 + ko);
            cpa16(sb + dB,  pb + ko);
            CPA_COMMIT();
        }
        const u32 sb = sm0 + (u32)(kt % NSTAGE) * STAGE_BYTES;
        #pragma unroll
        for (int ks = 0; ks < 2; ks++) {
            u32 ah[2][4], bh[2][4];
            #pragma unroll
            for (int mi = 0; mi < 2; mi++)
                ldsm4(ah[mi], sb + OFF_A + a_off + (u32)(mi * 16 * PITCH) + (u32)(ks * 32));
            ldsm4(bh[0], sb + OFF_B + b_off0 + (u32)(ks * 32));
            ldsm4(bh[1], sb + OFF_B + b_off1 + (u32)(ks * 32));
            #pragma unroll
            for (int mi = 0; mi < 2; mi++) {
                #pragma unroll
                for (int ni = 0; ni < 4; ni++) {
                    const int g = ni >> 1, s = (ni & 1) * 2;
                    mma16816(acc[mi][ni], ah[mi], bh[g][s], bh[g][s + 1]);
                }
            }
        }
    }

    // ---- epilogue: scale by routing weight, atomicAdd into out ----
    #pragma unroll
    for (int mi = 0; mi < 2; mi++) {
        const int r0o = wm * 32 + mi * 16 + (lane >> 2);
        const int r1o = r0o + 8;
        if (r0o < rows) {
            const float w0 = g_w[base + r0o];
            float* dst0 = out + (size_t)g_perm[base + r0o] * HID;
            #pragma unroll
            for (int ni = 0; ni < 4; ni++) {
                const int cc = n0 + wn * 32 + ni * 8 + 2 * (lane & 3);
                atomicAdd(dst0 + cc,     w0 * acc[mi][ni][0]);
                atomicAdd(dst0 + cc + 1, w0 * acc[mi][ni][1]);
            }
        }
        if (r1o < rows) {
            const float w1 = g_w[base + r1o];
            float* dst1 = out + (size_t)g_perm[base + r1o] * HID;
            #pragma unroll
            for (int ni = 0; ni < 4; ni++) {
                const int cc = n0 + wn * 32 + ni * 8 + 2 * (lane & 3);
                atomicAdd(dst1 + cc,     w1 * acc[mi][ni][2]);
                atomicAdd(dst1 + cc + 1, w1 * acc[mi][ni][3]);
            }
        }
    }
}

// ---- launch -------------------------------------------------------------------------
extern "C" void kernel_launch(void* const* d_in, const int* in_sizes, int n_in,
                              void* d_out, int out_size) {
    if (n_in < 5) return;
    const float* x  = (const float*)d_in[0];
    const float* Wr = (const float*)d_in[1];
    const float* Wg = (const float*)d_in[2];
    const float* Wu = (const float*)d_in[3];
    const float* Wd = (const float*)d_in[4];
    float* out = (float*)d_out;

    int T = in_sizes[0] / HID;
    if (T > MAXT) T = MAXT;

    cudaFuncSetAttribute(gateup_mma_kernel, cudaFuncAttributeMaxDynamicSharedMemorySize, SMEM_DYN);
    cudaFuncSetAttribute(down_mma_kernel,   cudaFuncAttributeMaxDynamicSharedMemorySize, SMEM_DYN);

    const int write_logits = (out_size >= T * HID + T * NEXP);
    float* logits = out + (size_t)T * HID;

    // zero the token-output region (accumulated via atomicAdd by down kernel)
    cudaMemsetAsync(out, 0, (size_t)T * HID * sizeof(float));

    router_kernel<<<T, 256>>>(x, Wr, logits, write_logits);
    offsets_kernel<<<1, 256>>>(T);
    scatter_kernel<<<(T + 255) / 256, 256>>>(T);

    const int nx = T * HID / 4;
    const int nw = NEXP * INTER * HID / 4;
    split_all_kernel<<<(nx + 3 * nw + 255) / 256, 256>>>(x, Wg, Wu, Wd, nx, nw);

    gateup_mma_kernel<<<dim3(INTER / 32, MAXSLOTS / 128, NEXP), 256, SMEM_DYN>>>();
    down_mma_kernel<<<dim3(HID / 64, MAXSLOTS / 128, NEXP), 256, SMEM_DYN>>>(out);
}

// round 17
// speedup vs baseline: 1.3160x; 1.0052x over previous
#include <cuda_runtime.h>
#include <cuda_fp16.h>
#include <cstdint>

// ============================================================================
// BiBoSparseMoeBlock: top-2-of-8 MoE SwiGLU, fp32 in/out.
// Round 17: R16 champion + router fuses the x fp32->fp16 conversion (it
// already stages each token row in smem); split kernel now converts only
// the 3 weight tensors. GEMMs/scatter/atomic-combine byte-identical to R16.
// ============================================================================

#define HID   2048
#define INTER 1024
#define NEXP  8
#define MAXT  4096
#define MAXSLOTS (2 * MAXT)

typedef unsigned int u32;

// ---- device scratch ---------------------------------------------------------
__device__ int   g_cnt[NEXP];
__device__ int   g_off[NEXP];
__device__ int   g_fill[NEXP];
__device__ int   g_perm[MAXSLOTS];
__device__ float g_w[MAXSLOTS];
__device__ int   g_tidx[MAXT * 2];
__device__ float g_tw[MAXT * 2];

__device__ __half g_X16[(size_t)MAXT * HID];
__device__ __half g_Wg16[(size_t)NEXP * INTER * HID];
__device__ __half g_Wu16[(size_t)NEXP * INTER * HID];
__device__ __half g_Wd16[(size_t)NEXP * HID * INTER];
__device__ __half g_H16[(size_t)MAXSLOTS * INTER];

// ---- PTX helpers (baseline sm_80-era only) -------------------------------------
__device__ __forceinline__ u32 smem_u32(const void* p) {
    u32 a;
    asm("{ .reg .u64 t; cvta.to.shared.u64 t, %1; cvt.u32.u64 %0, t; }" : "=r"(a) : "l"(p));
    return a;
}
__device__ __forceinline__ void cpa16(u32 dst, const void* src) {
    asm volatile("cp.async.cg.shared.global [%0], [%1], 16;" :: "r"(dst), "l"(src));
}
#define CPA_COMMIT() asm volatile("cp.async.commit_group;" ::: "memory")
#define CPA_WAIT1()  asm volatile("cp.async.wait_group 1;" ::: "memory")
#define CPA_WAIT0()  asm volatile("cp.async.wait_group 0;" ::: "memory")

__device__ __forceinline__ void ldsm4(u32* r, u32 addr) {
    asm volatile("ldmatrix.sync.aligned.m8n8.x4.shared.b16 {%0,%1,%2,%3}, [%4];"
                 : "=r"(r[0]), "=r"(r[1]), "=r"(r[2]), "=r"(r[3]) : "r"(addr));
}
__device__ __forceinline__ void mma16816(float* c, const u32* a, u32 b0, u32 b1) {
    asm volatile(
        "mma.sync.aligned.m16n8k16.row.col.f32.f16.f16.f32 "
        "{%0,%1,%2,%3}, {%4,%5,%6,%7}, {%8,%9}, {%0,%1,%2,%3};"
        : "+f"(c[0]), "+f"(c[1]), "+f"(c[2]), "+f"(c[3])
        : "r"(a[0]), "r"(a[1]), "r"(a[2]), "r"(a[3]), "r"(b0), "r"(b1));
}

// ---- smem geometry: BK=32 fp16 rows (64B data), pitch 80B ----------------------
#define PITCH 80
#define OFF_A  0              // 128 rows * 80 = 10240
#define OFF_B  10240          // 64 rows * 80 = 5120
#define STAGE_BYTES 15360
#define NSTAGE 3
#define SMEM_DYN (NSTAGE * STAGE_BYTES)   // 46080 -> 2 CTAs/SM

// ---- fp32x4 -> fp16x4 helper ------------------------------------------------------
__device__ __forceinline__ uint2 f4_to_h4(const float4 v) {
    __half2 a = __floats2half2_rn(v.x, v.y);
    __half2 b = __floats2half2_rn(v.z, v.w);
    return make_uint2(*(u32*)&a, *(u32*)&b);
}

// ---- router: logits, top-2, softmax, AND x fp16 conversion ------------------------
__global__ void router_kernel(const float* __restrict__ x,
                              const float* __restrict__ Wr,
                              float* __restrict__ logits_out, int write_logits) {
    const int t = blockIdx.x;
    const int warp = threadIdx.x >> 5;
    const int lane = threadIdx.x & 31;
    __shared__ float xs[HID];           // 8 KB: stage the token row ONCE
    __shared__ float slog[NEXP];

    const float4* xr = (const float4*)(x + (size_t)t * HID);
    for (int i = threadIdx.x; i < HID / 4; i += 256)
        ((float4*)xs)[i] = xr[i];
    __syncthreads();

    // fused: convert the staged row to fp16 (coalesced uint2 stores)
    {
        uint2* dst = (uint2*)(g_X16 + (size_t)t * HID);
        for (int i = threadIdx.x; i < HID / 4; i += 256)
            dst[i] = f4_to_h4(((const float4*)xs)[i]);
    }

    const float* wr = Wr + (size_t)warp * HID;
    float s = 0.0f;
    #pragma unroll 4
    for (int i = lane; i < HID; i += 32) s += xs[i] * wr[i];
    #pragma unroll
    for (int o = 16; o > 0; o >>= 1) s += __shfl_xor_sync(0xffffffffu, s, o);
    if (lane == 0) slog[warp] = s;
    __syncthreads();
    if (write_logits && threadIdx.x < NEXP)
        logits_out[t * NEXP + threadIdx.x] = slog[threadIdx.x];
    if (threadIdx.x == 0) {
        float v0 = -1e30f; int i0 = 0;
        #pragma unroll
        for (int i = 0; i < NEXP; i++) if (slog[i] > v0) { v0 = slog[i]; i0 = i; }
        float v1 = -1e30f; int i1 = 0;
        #pragma unroll
        for (int i = 0; i < NEXP; i++)
            if (i != i0 && slog[i] > v1) { v1 = slog[i]; i1 = i; }
        float ex = expf(v1 - v0);
        float inv = 1.0f / (1.0f + ex);
        g_tidx[2 * t] = i0; g_tidx[2 * t + 1] = i1;
        g_tw[2 * t] = inv;  g_tw[2 * t + 1] = ex * inv;
    }
}

// counting offsets: histogram g_tidx in one block; also zeroes g_fill
__global__ void offsets_kernel(int T) {
    __shared__ int hist[NEXP];
    if (threadIdx.x < NEXP) hist[threadIdx.x] = 0;
    __syncthreads();
    for (int i = threadIdx.x; i < 2 * T; i += blockDim.x)
        atomicAdd(&hist[g_tidx[i]], 1);
    __syncthreads();
    if (threadIdx.x == 0) {
        int o = 0;
        #pragma unroll
        for (int e = 0; e < NEXP; e++) {
            g_cnt[e] = hist[e];
            g_off[e] = o;
            g_fill[e] = 0;
            o += hist[e];
        }
    }
}

__global__ void scatter_kernel(int T) {
    int t = blockIdx.x * blockDim.x + threadIdx.x;
    if (t >= T) return;
    #pragma unroll
    for (int j = 0; j < 2; j++) {
        int e = g_tidx[2 * t + j];
        int p = atomicAdd(&g_fill[e], 1);
        int slot = g_off[e] + p;
        g_perm[slot] = t;
        g_w[slot] = g_tw[2 * t + j];
    }
}

// ---- weight conversion: Wg, Wu, Wd fp32 -> fp16 -----------------------------------
__global__ void split_w_kernel(const float* __restrict__ Wg,
                               const float* __restrict__ Wu,
                               const float* __restrict__ Wd, int nw) {
    int i = blockIdx.x * blockDim.x + threadIdx.x;
    if (i < nw) {
        ((uint2*)g_Wg16)[i] = f4_to_h4(((const float4*)Wg)[i]);
    } else if (i < 2 * nw) {
        int j = i - nw;
        ((uint2*)g_Wu16)[j] = f4_to_h4(((const float4*)Wu)[j]);
    } else if (i < 3 * nw) {
        int j = i - 2 * nw;
        ((uint2*)g_Wd16)[j] = f4_to_h4(((const float4*)Wd)[j]);
    }
}

// ---- GEMM 1: gate+up. CTA: 128 slots x (32 gate + 32 up), warp tile 32x32 -------
__global__ __launch_bounds__(256, 2) void gateup_mma_kernel() {
    const int e   = blockIdx.z;
    const int cnt = g_cnt[e];
    const int m0  = blockIdx.y * 128;
    if (m0 >= cnt) return;
    const int rows = min(cnt - m0, 128);
    const int base = g_off[e] + m0;
    const int n0   = blockIdx.x * 32;

    extern __shared__ char dsm[];
    const u32 sm0 = smem_u32(dsm);

    const int tid  = threadIdx.x;
    const int lane = tid & 31;
    const int wid  = tid >> 5;
    const int wm   = wid >> 1;          // 0..3 -> 32-row band
    const int wn   = wid & 1;           // 0 = gate cols, 1 = up cols

    // ---- loader: 3 cp.async per thread per stage ----
    const int q = tid >> 2;             // 0..63
    const int c = tid & 3;
    const int r0 = min(q, rows - 1);
    const int r1 = min(q + 64, rows - 1);
    const size_t xo0 = (size_t)g_perm[base + r0] * HID + c * 8;
    const size_t xo1 = (size_t)g_perm[base + r1] * HID + c * 8;
    const __half* pb;
    if (q < 32) pb = g_Wg16 + ((size_t)e * INTER + n0 + q) * HID + c * 8;
    else        pb = g_Wu16 + ((size_t)e * INTER + n0 + (q - 32)) * HID + c * 8;

    const u32 dA0 = (u32)(OFF_A + q * PITCH + c * 16);
    const u32 dA1 = dA0 + 64 * PITCH;
    const u32 dB  = (u32)(OFF_B + q * PITCH + c * 16);

    // ---- ldmatrix bases: warp tile 32 rows x 32 B-rows ----
    const u32 a_off = (u32)((wm * 32 + (lane & 7) + ((lane >> 3) & 1) * 8) * PITCH
                    + (lane >> 4) * 16);
    const u32 b_off0 = (u32)((wn * 32 + (lane & 7) + (lane >> 4) * 8) * PITCH
                    + ((lane >> 3) & 1) * 16);
    const u32 b_off1 = b_off0 + 16 * PITCH;

    float acc[2][4][4];
    #pragma unroll
    for (int i = 0; i < 2; i++)
        #pragma unroll
        for (int j = 0; j < 4; j++)
            #pragma unroll
            for (int k = 0; k < 4; k++) acc[i][j][k] = 0.0f;

    const int KT = HID / 32;            // 64

    #pragma unroll
    for (int p = 0; p < NSTAGE - 1; p++) {
        const u32 sb = sm0 + (u32)p * STAGE_BYTES;
        const size_t ko = (size_t)p * 32;
        cpa16(sb + dA0, g_X16 + xo0 + ko);
        cpa16(sb + dA1, g_X16 + xo1 + ko);
        cpa16(sb + dB,  pb + ko);
        CPA_COMMIT();
    }

    #pragma unroll 1
    for (int kt = 0; kt < KT; kt++) {
        if (kt == KT - 1) CPA_WAIT0(); else CPA_WAIT1();
        __syncthreads();
        if (kt + NSTAGE - 1 < KT) {
            const u32 sb = sm0 + (u32)((kt + NSTAGE - 1) % NSTAGE) * STAGE_BYTES;
            const size_t ko = (size_t)(kt + NSTAGE - 1) * 32;
            cpa16(sb + dA0, g_X16 + xo0 + ko);
            cpa16(sb + dA1, g_X16 + xo1 + ko);
            cpa16(sb + dB,  pb + ko);
            CPA_COMMIT();
        }
        const u32 sb = sm0 + (u32)(kt % NSTAGE) * STAGE_BYTES;
        #pragma unroll
        for (int ks = 0; ks < 2; ks++) {
            u32 ah[2][4], bh[2][4];
            #pragma unroll
            for (int mi = 0; mi < 2; mi++)
                ldsm4(ah[mi], sb + OFF_A + a_off + (u32)(mi * 16 * PITCH) + (u32)(ks * 32));
            ldsm4(bh[0], sb + OFF_B + b_off0 + (u32)(ks * 32));
            ldsm4(bh[1], sb + OFF_B + b_off1 + (u32)(ks * 32));
            #pragma unroll
            for (int mi = 0; mi < 2; mi++) {
                #pragma unroll
                for (int ni = 0; ni < 4; ni++) {
                    const int g = ni >> 1, s = (ni & 1) * 2;
                    mma16816(acc[mi][ni], ah[mi], bh[g][s], bh[g][s + 1]);
                }
            }
        }
    }
    __syncthreads();

    // ---- epilogue: exchange via smem (128 x 72 f32), silu(g)*u, store fp16 ----
    float* S = (float*)dsm;
    #pragma unroll
    for (int mi = 0; mi < 2; mi++) {
        const int rr = wm * 32 + mi * 16 + (lane >> 2);
        #pragma unroll
        for (int ni = 0; ni < 4; ni++) {
            const int cc = wn * 32 + ni * 8 + 2 * (lane & 3);
            *(float2*)(S + (size_t)rr * 72 + cc)       = make_float2(acc[mi][ni][0], acc[mi][ni][1]);
            *(float2*)(S + (size_t)(rr + 8) * 72 + cc) = make_float2(acc[mi][ni][2], acc[mi][ni][3]);
        }
    }
    __syncthreads();
    {
        const int row  = tid >> 1;
        const int half = (tid & 1) * 16;
        if (row < rows) {
            u32 ph[8];
            #pragma unroll
            for (int p = 0; p < 8; p++) {
                float g0 = S[(size_t)row * 72 + half + 2 * p];
                float g1 = S[(size_t)row * 72 + half + 2 * p + 1];
                float u0 = S[(size_t)row * 72 + 32 + half + 2 * p];
                float u1 = S[(size_t)row * 72 + 32 + half + 2 * p + 1];
                float h0 = (g0 / (1.0f + expf(-g0))) * u0;
                float h1 = (g1 / (1.0f + expf(-g1))) * u1;
                __half2 A = __floats2half2_rn(h0, h1);
                ph[p] = *(u32*)&A;
            }
            u32* dh = (u32*)(g_H16 + (size_t)(base + row) * INTER + n0 + half);
            ((uint4*)dh)[0] = make_uint4(ph[0], ph[1], ph[2], ph[3]);
            ((uint4*)dh)[1] = make_uint4(ph[4], ph[5], ph[6], ph[7]);
        }
    }
}

// ---- GEMM 2: down. CTA: 128 slots x 64 hid, warp tile 32x32, K=1024 --------------
// Epilogue atomicAdds weighted results directly into out (2 contribs/element).
__global__ __launch_bounds__(256, 2) void down_mma_kernel(float* __restrict__ out) {
    const int e   = blockIdx.z;
    const int cnt = g_cnt[e];
    const int m0  = blockIdx.y * 128;
    if (m0 >= cnt) return;
    const int rows = min(cnt - m0, 128);
    const int base = g_off[e] + m0;
    const int n0   = blockIdx.x * 64;

    extern __shared__ char dsm[];
    const u32 sm0 = smem_u32(dsm);

    const int tid  = threadIdx.x;
    const int lane = tid & 31;
    const int wid  = tid >> 5;
    const int wm   = wid >> 1;
    const int wn   = wid & 1;

    const int q = tid >> 2;
    const int c = tid & 3;
    const int r0 = min(q, rows - 1);
    const int r1 = min(q + 64, rows - 1);
    const size_t ho0 = (size_t)(base + r0) * INTER + c * 8;
    const size_t ho1 = (size_t)(base + r1) * INTER + c * 8;
    const __half* pb = g_Wd16 + ((size_t)e * HID + n0 + q) * INTER + c * 8;

    const u32 dA0 = (u32)(OFF_A + q * PITCH + c * 16);
    const u32 dA1 = dA0 + 64 * PITCH;
    const u32 dB  = (u32)(OFF_B + q * PITCH + c * 16);

    const u32 a_off = (u32)((wm * 32 + (lane & 7) + ((lane >> 3) & 1) * 8) * PITCH
                    + (lane >> 4) * 16);
    const u32 b_off0 = (u32)((wn * 32 + (lane & 7) + (lane >> 4) * 8) * PITCH
                    + ((lane >> 3) & 1) * 16);
    const u32 b_off1 = b_off0 + 16 * PITCH;

    float acc[2][4][4];
    #pragma unroll
    for (int i = 0; i < 2; i++)
        #pragma unroll
        for (int j = 0; j < 4; j++)
            #pragma unroll
            for (int k = 0; k < 4; k++) acc[i][j][k] = 0.0f;

    const int KT = INTER / 32;          // 32

    #pragma unroll
    for (int p = 0; p < NSTAGE - 1; p++) {
        const u32 sb = sm0 + (u32)p * STAGE_BYTES;
        const size_t ko = (size_t)p * 32;
        cpa16(sb + dA0, g_H16 + ho0 + ko);
        cpa16(sb + dA1, g_H16 + ho1 + ko);
        cpa16(sb + dB,  pb + ko);
        CPA_COMMIT();
    }

    #pragma unroll 1
    for (int kt = 0; kt < KT; kt++) {
        if (kt == KT - 1) CPA_WAIT0(); else CPA_WAIT1();
        __syncthreads();
        if (kt + NSTAGE - 1 < KT) {
            const u32 sb = sm0 + (u32)((kt + NSTAGE - 1) % NSTAGE) * STAGE_BYTES;
            const size_t ko = (size_t)(kt + NSTAGE - 1) * 32;
            cpa16(sb + dA0, g_H16 + ho0 + ko);
            cpa16(sb + dA1, g_H16 + ho1 + ko);
            cpa16(sb + dB,  pb + ko);
            CPA_COMMIT();
        }
        const u32 sb = sm0 + (u32)(kt % NSTAGE) * STAGE_BYTES;
        #pragma unroll
        for (int ks = 0; ks < 2; ks++) {
            u32 ah[2][4], bh[2][4];
            #pragma unroll
            for (int mi = 0; mi < 2; mi++)
                ldsm4(ah[mi], sb + OFF_A + a_off + (u32)(mi * 16 * PITCH) + (u32)(ks * 32));
            ldsm4(bh[0], sb + OFF_B + b_off0 + (u32)(ks * 32));
            ldsm4(bh[1], sb + OFF_B + b_off1 + (u32)(ks * 32));
            #pragma unroll
            for (int mi = 0; mi < 2; mi++) {
                #pragma unroll
                for (int ni = 0; ni < 4; ni++) {
                    const int g = ni >> 1, s = (ni & 1) * 2;
                    mma16816(acc[mi][ni], ah[mi], bh[g][s], bh[g][s + 1]);
                }
            }
        }
    }

    // ---- epilogue: scale by routing weight, atomicAdd into out ----
    #pragma unroll
    for (int mi = 0; mi < 2; mi++) {
        const int r0o = wm * 32 + mi * 16 + (lane >> 2);
        const int r1o = r0o + 8;
        if (r0o < rows) {
            const float w0 = g_w[base + r0o];
            float* dst0 = out + (size_t)g_perm[base + r0o] * HID;
            #pragma unroll
            for (int ni = 0; ni < 4; ni++) {
                const int cc = n0 + wn * 32 + ni * 8 + 2 * (lane & 3);
                atomicAdd(dst0 + cc,     w0 * acc[mi][ni][0]);
                atomicAdd(dst0 + cc + 1, w0 * acc[mi][ni][1]);
            }
        }
        if (r1o < rows) {
            const float w1 = g_w[base + r1o];
            float* dst1 = out + (size_t)g_perm[base + r1o] * HID;
            #pragma unroll
            for (int ni = 0; ni < 4; ni++) {
                const int cc = n0 + wn * 32 + ni * 8 + 2 * (lane & 3);
                atomicAdd(dst1 + cc,     w1 * acc[mi][ni][2]);
                atomicAdd(dst1 + cc + 1, w1 * acc[mi][ni][3]);
            }
        }
    }
}

// ---- launch -------------------------------------------------------------------------
extern "C" void kernel_launch(void* const* d_in, const int* in_sizes, int n_in,
                              void* d_out, int out_size) {
    if (n_in < 5) return;
    const float* x  = (const float*)d_in[0];
    const float* Wr = (const float*)d_in[1];
    const float* Wg = (const float*)d_in[2];
    const float* Wu = (const float*)d_in[3];
    const float* Wd = (const float*)d_in[4];
    float* out = (float*)d_out;

    int T = in_sizes[0] / HID;
    if (T > MAXT) T = MAXT;

    cudaFuncSetAttribute(gateup_mma_kernel, cudaFuncAttributeMaxDynamicSharedMemorySize, SMEM_DYN);
    cudaFuncSetAttribute(down_mma_kernel,   cudaFuncAttributeMaxDynamicSharedMemorySize, SMEM_DYN);

    const int write_logits = (out_size >= T * HID + T * NEXP);
    float* logits = out + (size_t)T * HID;

    // zero the token-output region (accumulated via atomicAdd by down kernel)
    cudaMemsetAsync(out, 0, (size_t)T * HID * sizeof(float));

    router_kernel<<<T, 256>>>(x, Wr, logits, write_logits);
    offsets_kernel<<<1, 256>>>(T);
    scatter_kernel<<<(T + 255) / 256, 256>>>(T);

    const int nw = NEXP * INTER * HID / 4;
    split_w_kernel<<<(3 * nw + 255) / 256, 256>>>(Wg, Wu, Wd, nw);

    gateup_mma_kernel<<<dim3(INTER / 32, MAXSLOTS / 128, NEXP), 256, SMEM_DYN>>>();
    down_mma_kernel<<<dim3(HID / 64, MAXSLOTS / 128, NEXP), 256, SMEM_DYN>>>(out);
}